// round 11
// baseline (speedup 1.0000x reference)
#include <cuda_runtime.h>
#include <cuda_bf16.h>
#include <cstdint>

// ============================================================================
// Swin window attention (quadratic norm), all-tensor split-bf16 pipeline:
//   1) split_x; prep_small (w splits + bias matrix)
//   2) QKV GEMM (128x128 tile, K-chunk 32, 80KB smem, 2 CTAs/SM) -> split qkv
//   3) attention: HMMA, score fragments stay in registers        [slot 4]
//   4) proj GEMM + bias -> out (fp32)
// ============================================================================

#define NW     49
#define DIMC   384
#define NH     12
#define HD     32
#define SCALEF 0.17677669529663687f
#define MTOT   200704            // 4096 * 49 = 1568 * 128
#define NQKV   1152

typedef unsigned long long ull;

// ---- scratch (device globals) -----------------------------------------------
__device__ __nv_bfloat16 g_xh[(size_t)MTOT * DIMC];
__device__ __nv_bfloat16 g_xl[(size_t)MTOT * DIMC];
__device__ __nv_bfloat16 g_wqkvT_h[NQKV * DIMC];
__device__ __nv_bfloat16 g_wqkvT_l[NQKV * DIMC];
__device__ __nv_bfloat16 g_wprojT_h[DIMC * DIMC];
__device__ __nv_bfloat16 g_wprojT_l[DIMC * DIMC];
__device__ __nv_bfloat16 g_qkvh[(size_t)MTOT * NQKV];
__device__ __nv_bfloat16 g_qkvl[(size_t)MTOT * NQKV];
__device__ __nv_bfloat16 g_ah[(size_t)MTOT * DIMC];
__device__ __nv_bfloat16 g_al[(size_t)MTOT * DIMC];
__device__ float         g_bias_m[NH * NW * NW];   // bias[h][r][c]

// ---- helpers ------------------------------------------------------------------
__device__ __forceinline__ uint32_t smem_to_u32(const void* p) {
    uint32_t a;
    asm("{ .reg .u64 t; cvta.to.shared.u64 t, %1; cvt.u32.u64 %0, t; }"
        : "=r"(a) : "l"(p));
    return a;
}
__device__ __forceinline__ void ldsm_x4(uint32_t& r0, uint32_t& r1,
                                        uint32_t& r2, uint32_t& r3, uint32_t a) {
    asm volatile("ldmatrix.sync.aligned.m8n8.x4.shared.b16 {%0,%1,%2,%3}, [%4];"
                 : "=r"(r0), "=r"(r1), "=r"(r2), "=r"(r3) : "r"(a));
}
__device__ __forceinline__ void ldsm_x2(uint32_t& r0, uint32_t& r1, uint32_t a) {
    asm volatile("ldmatrix.sync.aligned.m8n8.x2.shared.b16 {%0,%1}, [%2];"
                 : "=r"(r0), "=r"(r1) : "r"(a));
}
__device__ __forceinline__ void ldsm_x4t(uint32_t& r0, uint32_t& r1,
                                         uint32_t& r2, uint32_t& r3, uint32_t a) {
    asm volatile("ldmatrix.sync.aligned.m8n8.x4.trans.shared.b16 {%0,%1,%2,%3}, [%4];"
                 : "=r"(r0), "=r"(r1), "=r"(r2), "=r"(r3) : "r"(a));
}
__device__ __forceinline__ void mma_bf16(float* d, const uint32_t* a, const uint32_t* b) {
    asm volatile("mma.sync.aligned.m16n8k16.row.col.f32.bf16.bf16.f32 "
                 "{%0,%1,%2,%3}, {%4,%5,%6,%7}, {%8,%9}, {%0,%1,%2,%3};"
                 : "+f"(d[0]), "+f"(d[1]), "+f"(d[2]), "+f"(d[3])
                 : "r"(a[0]), "r"(a[1]), "r"(a[2]), "r"(a[3]), "r"(b[0]), "r"(b[1]));
}
__device__ __forceinline__ void cp16(uint32_t dst, const void* src) {
    asm volatile("cp.async.cg.shared.global [%0], [%1], 16;" :: "r"(dst), "l"(src));
}
#define CP_COMMIT() asm volatile("cp.async.commit_group;" ::: "memory")
#define CP_WAIT(n)  asm volatile("cp.async.wait_group %0;" :: "n"(n) : "memory")

__device__ __forceinline__ void split2(float v, __nv_bfloat16& h, __nv_bfloat16& l) {
    h = __float2bfloat16(v);
    l = __float2bfloat16(v - __bfloat162float(h));
}
__device__ __forceinline__ void pack_split(float a, float b, uint32_t& ph, uint32_t& pl) {
    __nv_bfloat16 ha, la, hb, lb;
    split2(a, ha, la); split2(b, hb, lb);
    __nv_bfloat162 vh = { ha, hb }, vl = { la, lb };
    ph = *(uint32_t*)&vh;
    pl = *(uint32_t*)&vl;
}

// ============================================================================
// Kernel 1: split x (fp32 -> bf16 hi/lo)
// ============================================================================
__global__ void split_x_kernel(const float* __restrict__ x,
                               __nv_bfloat16* __restrict__ xh,
                               __nv_bfloat16* __restrict__ xl, int n4) {
    int i = blockIdx.x * 256 + threadIdx.x;
    if (i >= n4) return;
    float4 v = ((const float4*)x)[i];
    __nv_bfloat16 h0, h1, h2, h3, l0, l1, l2, l3;
    split2(v.x, h0, l0); split2(v.y, h1, l1);
    split2(v.z, h2, l2); split2(v.w, h3, l3);
    ushort4 hv = { __bfloat16_as_ushort(h0), __bfloat16_as_ushort(h1),
                   __bfloat16_as_ushort(h2), __bfloat16_as_ushort(h3) };
    ushort4 lv = { __bfloat16_as_ushort(l0), __bfloat16_as_ushort(l1),
                   __bfloat16_as_ushort(l2), __bfloat16_as_ushort(l3) };
    ((ushort4*)xh)[i] = hv;
    ((ushort4*)xl)[i] = lv;
}

// ============================================================================
// Kernel 2: merged small prep — wqkv split, wproj split, bias matrix
// ============================================================================
#define PREP_WQ 1728
#define PREP_WP (PREP_WQ + 576)
#define PREP_BM (PREP_WP + 113)

__global__ void prep_small_kernel(const float* __restrict__ wqkv,
                                  const float* __restrict__ wproj,
                                  const float* __restrict__ bt,
                                  const int* __restrict__ rel,
                                  __nv_bfloat16* __restrict__ wqh,
                                  __nv_bfloat16* __restrict__ wql,
                                  __nv_bfloat16* __restrict__ wph,
                                  __nv_bfloat16* __restrict__ wpl,
                                  float* __restrict__ bm) {
    int b = blockIdx.x;
    if (b < PREP_WQ) {
        int i = b * 256 + threadIdx.x;
        int n = i / DIMC, k = i - n * DIMC;
        __nv_bfloat16 h, l;
        split2(wqkv[(size_t)k * NQKV + n], h, l);
        wqh[i] = h; wql[i] = l;
    } else if (b < PREP_WP) {
        int i = (b - PREP_WQ) * 256 + threadIdx.x;
        int n = i / DIMC, k = i - n * DIMC;
        __nv_bfloat16 h, l;
        split2(wproj[(size_t)k * DIMC + n], h, l);
        wph[i] = h; wpl[i] = l;
    } else {
        int i = (b - PREP_WP) * 256 + threadIdx.x;
        if (i < NH * NW * NW) {
            int h = i / (NW * NW), idx = i - h * (NW * NW);
            bm[i] = bt[rel[idx] * NH + h];
        }
    }
}

// ============================================================================
// Kernel 3: split-bf16 HMMA GEMM. CTA tile 128x128, 8 warps (64x32 warp tile),
// K-chunk 32, 2-stage cp.async, 80 KB smem -> 2 CTAs/SM. Independent CTAs
// overlap each other's load phases against the tensor pipe.
// Tiles: 128 rows x 32 bf16, 80B row stride (conflict-free ldsm).
// ============================================================================
#define TILE_B   10240                 // 128 * 80
#define STAGE_B  (4 * TILE_B)          // 40960
#define GEMM_SMEM (2 * STAGE_B)        // 81920

__global__ void __launch_bounds__(256, 2)
gemm3_kernel(const __nv_bfloat16* __restrict__ Ah,
             const __nv_bfloat16* __restrict__ Al,
             const __nv_bfloat16* __restrict__ Bh,
             const __nv_bfloat16* __restrict__ Bl,
             float* __restrict__ Cf,
             __nv_bfloat16* __restrict__ Ch,
             __nv_bfloat16* __restrict__ Cl,
             int ldc,
             const float* __restrict__ bias) {
    extern __shared__ __align__(16) char smem[];
    const int tid  = threadIdx.x;
    const int warp = tid >> 5;
    const int lane = tid & 31;
    const uint32_t sb = smem_to_u32(smem);
    const int m0 = blockIdx.y * 128;
    const int n0 = blockIdx.x * 128;
    const int m_warp = (warp >> 2) * 64;   // 0 / 64
    const int n_warp = (warp & 3) * 32;    // 0..96

    float acc[4][4][4];
    #pragma unroll
    for (int mt = 0; mt < 4; ++mt)
        #pragma unroll
        for (int nt = 0; nt < 4; ++nt)
            #pragma unroll
            for (int e = 0; e < 4; ++e) acc[mt][nt][e] = 0.f;

    // stage loader: 4 tiles x 512 chunks of 16B -> 2 cp16 per thread per tile
    auto load_stage = [&](int stage, int ks) {
        const int k0 = ks * 32;
        const __nv_bfloat16* srcs[4] = { Ah, Al, Bh, Bl };
        const int r0s[4] = { m0, m0, n0, n0 };
        #pragma unroll
        for (int t = 0; t < 4; ++t) {
            const char* src = (const char*)(srcs[t] + (size_t)r0s[t] * DIMC + k0);
            uint32_t dst = sb + stage * STAGE_B + t * TILE_B;
            #pragma unroll
            for (int i = 0; i < 2; ++i) {
                int u = tid + i * 256;         // 0..511
                int row = u >> 2, ch = u & 3;
                cp16(dst + row * 80 + ch * 16,
                     src + (size_t)row * (DIMC * 2) + ch * 16);
            }
        }
    };

    load_stage(0, 0);
    CP_COMMIT();

    const int NKS = DIMC / 32;   // 12
    for (int ks = 0; ks < NKS; ++ks) {
        const int s = ks & 1;
        __syncthreads();
        if (ks + 1 < NKS) {
            load_stage(1 - s, ks + 1);
            CP_COMMIT();
            CP_WAIT(1);
        } else {
            CP_WAIT(0);
        }
        __syncthreads();

        const uint32_t ahBase = sb + s * STAGE_B;
        const uint32_t alBase = ahBase + TILE_B;
        const uint32_t bhBase = ahBase + 2 * TILE_B;
        const uint32_t blBase = ahBase + 3 * TILE_B;
        const int rB = lane & 7, jB = (lane >> 3) & 1;
        const int rA = lane & 7, jA8 = ((lane >> 3) & 1) * 8, kA16 = ((lane >> 4) & 1) * 16;

        #pragma unroll
        for (int kk = 0; kk < 2; ++kk) {
            uint32_t bh[4][2], bl[4][2];
            #pragma unroll
            for (int nt = 0; nt < 4; ++nt) {
                uint32_t off = (uint32_t)(n_warp + nt * 8 + rB) * 80 + kk * 32 + jB * 16;
                ldsm_x2(bh[nt][0], bh[nt][1], bhBase + off);
                ldsm_x2(bl[nt][0], bl[nt][1], blBase + off);
            }
            uint32_t ah[4][4], al[4][4];
            #pragma unroll
            for (int mt = 0; mt < 4; ++mt) {
                uint32_t off = (uint32_t)(m_warp + mt * 16 + jA8 + rA) * 80 + kk * 32 + kA16;
                ldsm_x4(ah[mt][0], ah[mt][1], ah[mt][2], ah[mt][3], ahBase + off);
                ldsm_x4(al[mt][0], al[mt][1], al[mt][2], al[mt][3], alBase + off);
            }
            // term-outer: same-accumulator MMAs are 16 apart
            #pragma unroll
            for (int mt = 0; mt < 4; ++mt)
                #pragma unroll
                for (int nt = 0; nt < 4; ++nt)
                    mma_bf16(acc[mt][nt], ah[mt], bh[nt]);
            #pragma unroll
            for (int mt = 0; mt < 4; ++mt)
                #pragma unroll
                for (int nt = 0; nt < 4; ++nt)
                    mma_bf16(acc[mt][nt], ah[mt], bl[nt]);
            #pragma unroll
            for (int mt = 0; mt < 4; ++mt)
                #pragma unroll
                for (int nt = 0; nt < 4; ++nt)
                    mma_bf16(acc[mt][nt], al[mt], bh[nt]);
        }
    }

    const int mrow  = m0 + m_warp + (lane >> 2);
    const int ncol0 = n0 + n_warp + (lane & 3) * 2;
    if (Cf) {
        #pragma unroll
        for (int mt = 0; mt < 4; ++mt) {
            #pragma unroll
            for (int nt = 0; nt < 4; ++nt) {
                int m = mrow + mt * 16;
                int n = ncol0 + nt * 8;
                float2 v0 = { acc[mt][nt][0], acc[mt][nt][1] };
                float2 v1 = { acc[mt][nt][2], acc[mt][nt][3] };
                if (bias) {
                    float2 bv = *(const float2*)&bias[n];
                    v0.x += bv.x; v0.y += bv.y; v1.x += bv.x; v1.y += bv.y;
                }
                *(float2*)&Cf[(size_t)m * ldc + n]       = v0;
                *(float2*)&Cf[(size_t)(m + 8) * ldc + n] = v1;
            }
        }
    } else {
        #pragma unroll
        for (int mt = 0; mt < 4; ++mt) {
            #pragma unroll
            for (int nt = 0; nt < 4; ++nt) {
                int m = mrow + mt * 16;
                int n = ncol0 + nt * 8;
                float sc = (n < DIMC) ? SCALEF : 1.0f;   // q columns pre-scaled
                uint32_t ph, pl;
                pack_split(acc[mt][nt][0] * sc, acc[mt][nt][1] * sc, ph, pl);
                *(uint32_t*)&Ch[(size_t)m * ldc + n] = ph;
                *(uint32_t*)&Cl[(size_t)m * ldc + n] = pl;
                pack_split(acc[mt][nt][2] * sc, acc[mt][nt][3] * sc, ph, pl);
                *(uint32_t*)&Ch[(size_t)(m + 8) * ldc + n] = ph;
                *(uint32_t*)&Cl[(size_t)(m + 8) * ldc + n] = pl;
            }
        }
    }
}

// ============================================================================
// Kernel 4: HMMA attention (unchanged from round 9 — registers-only A).
// ============================================================================
#define ATT_SMEM 30720

__global__ void __launch_bounds__(128, 5)
attn_kernel(const __nv_bfloat16* __restrict__ qkvh,
            const __nv_bfloat16* __restrict__ qkvl,
            const float* __restrict__ bias_m,
            __nv_bfloat16* __restrict__ oh,
            __nv_bfloat16* __restrict__ ol) {
    extern __shared__ __align__(16) char smem[];
    const uint32_t sb = smem_to_u32(smem);

    const int tid  = threadIdx.x;
    const int warp = tid >> 5;
    const int lane = tid & 31;
    const int head = blockIdx.x;
    const size_t base = (size_t)blockIdx.y * NW;
    const float* bmh = bias_m + head * (NW * NW);

    // ---- zero V pad rows 49-63 ----
    {
        uint4 z = {0, 0, 0, 0};
        for (int i = tid; i < 150; i += 128) {
            int t = i / 75, rem = i % 75;
            int rr = rem / 5, cc = rem % 5;
            *(uint4*)(smem + 20480 + t * 5120 + (49 + rr) * 80 + cc * 16) = z;
        }
    }

    // ---- copy q/k/v hi+lo: 1176 x 16B chunks ----
    #pragma unroll
    for (int it = 0; it < 10; ++it) {
        int c = tid + it * 128;
        if (c < NW * 24) {
            int r = c / 24, rem = c - r * 24;
            int arr = rem >> 2, ch = rem & 3;
            const __nv_bfloat16* src = (arr & 1) ? qkvl : qkvh;
            int seg = arr >> 1;
            const char* s = (const char*)(src + (base + r) * NQKV + seg * DIMC
                                          + head * HD) + ch * 16;
            uint32_t dtile = ((arr & 1) ? 5120u : 0u) + (uint32_t)(arr >> 1) * 10240u;
            *(uint4*)(smem + dtile + r * 80 + ch * 16) = *(const uint4*)s;
        }
    }
    __syncthreads();

    const int rA = lane & 7, jA8 = ((lane >> 3) & 1) * 8, kA16 = ((lane >> 4) & 1) * 16;
    const int rB4 = (lane & 7) + ((lane >> 4) << 3);
    const int kB16 = ((lane >> 3) & 1) * 16;

    // ---- phase 1: S = Q K^T ----
    float s[7][4];
    #pragma unroll
    for (int j = 0; j < 7; ++j)
        #pragma unroll
        for (int e = 0; e < 4; ++e) s[j][e] = 0.f;

    #pragma unroll
    for (int kk = 0; kk < 2; ++kk) {
        uint32_t offA = (uint32_t)(16 * warp + jA8 + rA) * 80 + kk * 32 + kA16;
        uint32_t qh[4], ql[4];
        ldsm_x4(qh[0], qh[1], qh[2], qh[3], sb + offA);
        ldsm_x4(ql[0], ql[1], ql[2], ql[3], sb + 5120 + offA);
        uint32_t kh[7][2], kl[7][2];
        #pragma unroll
        for (int p = 0; p < 3; ++p) {
            uint32_t off = (uint32_t)(16 * p + rB4) * 80 + kk * 32 + kB16;
            ldsm_x4(kh[2*p][0], kh[2*p][1], kh[2*p+1][0], kh[2*p+1][1], sb + 10240 + off);
            ldsm_x4(kl[2*p][0], kl[2*p][1], kl[2*p+1][0], kl[2*p+1][1], sb + 15360 + off);
        }
        {
            uint32_t off = (uint32_t)(48 + (lane & 7)) * 80 + kk * 32
                           + ((lane >> 3) & 1) * 16;
            ldsm_x2(kh[6][0], kh[6][1], sb + 10240 + off);
            ldsm_x2(kl[6][0], kl[6][1], sb + 15360 + off);
        }
        #pragma unroll
        for (int j = 0; j < 7; ++j) mma_bf16(s[j], qh, kh[j]);
        #pragma unroll
        for (int j = 0; j < 7; ++j) mma_bf16(s[j], qh, kl[j]);
        #pragma unroll
        for (int j = 0; j < 7; ++j) mma_bf16(s[j], ql, kh[j]);
    }

    // ---- phase 2 (registers): bias + square -> packed A fragments + rowsum ----
    const int qd = lane >> 2;
    const int e2 = (lane & 3) * 2;
    const int r0 = 16 * warp + qd;
    const int r1 = r0 + 8;
    const bool r0v = (r0 < NW), r1v = (r1 < NW);
    uint32_t ah_t[4][4], al_t[4][4];
    float sum0 = 0.f, sum1 = 0.f;
    #pragma unroll
    for (int j = 0; j < 7; ++j) {
        int c = j * 8 + e2;
        bool c0v = (c < NW), c1v = (c + 1 < NW);
        float a00 = 0.f, a01 = 0.f, a10 = 0.f, a11 = 0.f;
        if (r0v && c0v) { float t = s[j][0] + __ldg(bmh + r0 * NW + c);     a00 = t * t; }
        if (r0v && c1v) { float t = s[j][1] + __ldg(bmh + r0 * NW + c + 1); a01 = t * t; }
        if (r1v && c0v) { float t = s[j][2] + __ldg(bmh + r1 * NW + c);     a10 = t * t; }
        if (r1v && c1v) { float t = s[j][3] + __ldg(bmh + r1 * NW + c + 1); a11 = t * t; }
        sum0 += a00 + a01;
        sum1 += a10 + a11;
        int t = j >> 1, hbase = (j & 1) * 2;
        pack_split(a00, a01, ah_t[t][hbase + 0], al_t[t][hbase + 0]);
        pack_split(a10, a11, ah_t[t][hbase + 1], al_t[t][hbase + 1]);
    }
    ah_t[3][2] = 0u; ah_t[3][3] = 0u;
    al_t[3][2] = 0u; al_t[3][3] = 0u;
    sum0 += __shfl_xor_sync(0xFFFFFFFFu, sum0, 1);
    sum0 += __shfl_xor_sync(0xFFFFFFFFu, sum0, 2);
    sum1 += __shfl_xor_sync(0xFFFFFFFFu, sum1, 1);
    sum1 += __shfl_xor_sync(0xFFFFFFFFu, sum1, 2);
    const float rs0 = 1.0f / (sum0 + 1e-6f);
    const float rs1 = 1.0f / (sum1 + 1e-6f);

    // ---- phase 3: O = A V ----
    float o[4][4];
    #pragma unroll
    for (int n = 0; n < 4; ++n)
        #pragma unroll
        for (int e = 0; e < 4; ++e) o[n][e] = 0.f;

    #pragma unroll
    for (int kk = 0; kk < 4; ++kk) {
        int kv = kk * 16 + ((lane >> 3) & 1) * 8 + (lane & 7);
        uint32_t off0 = (uint32_t)kv * 80 + ((lane >> 4) * 8) * 2;
        uint32_t off1 = off0 + 32;
        uint32_t vh[4][2], vl[4][2];
        ldsm_x4t(vh[0][0], vh[0][1], vh[1][0], vh[1][1], sb + 20480 + off0);
        ldsm_x4t(vh[2][0], vh[2][1], vh[3][0], vh[3][1], sb + 20480 + off1);
        ldsm_x4t(vl[0][0], vl[0][1], vl[1][0], vl[1][1], sb + 25600 + off0);
        ldsm_x4t(vl[2][0], vl[2][1], vl[3][0], vl[3][1], sb + 25600 + off1);
        #pragma unroll
        for (int n = 0; n < 4; ++n) mma_bf16(o[n], ah_t[kk], vh[n]);
        #pragma unroll
        for (int n = 0; n < 4; ++n) mma_bf16(o[n], ah_t[kk], vl[n]);
        #pragma unroll
        for (int n = 0; n < 4; ++n) mma_bf16(o[n], al_t[kk], vh[n]);
    }

    // ---- phase 4: normalize + split-bf16 store ----
    #pragma unroll
    for (int n = 0; n < 4; ++n) {
        int d = n * 8 + e2;
        if (r0v) {
            uint32_t ph, pl;
            pack_split(o[n][0] * rs0, o[n][1] * rs0, ph, pl);
            size_t oi = (base + r0) * DIMC + head * HD + d;
            *(uint32_t*)&oh[oi] = ph;
            *(uint32_t*)&ol[oi] = pl;
        }
        if (r1v) {
            uint32_t ph, pl;
            pack_split(o[n][2] * rs1, o[n][3] * rs1, ph, pl);
            size_t oi = (base + r1) * DIMC + head * HD + d;
            *(uint32_t*)&oh[oi] = ph;
            *(uint32_t*)&ol[oi] = pl;
        }
    }
}

// ============================================================================
// launch — attn stays the 4th launch (profiled slot)
// ============================================================================
extern "C" void kernel_launch(void* const* d_in, const int* in_sizes, int n_in,
                              void* d_out, int out_size) {
    const float* x          = (const float*)d_in[0];
    const float* w_qkv      = (const float*)d_in[1];
    const float* w_proj     = (const float*)d_in[2];
    const float* b_proj     = (const float*)d_in[3];
    const float* bias_table = (const float*)d_in[4];
    const int*   rel_idx    = (const int*)d_in[5];
    float* out = (float*)d_out;

    void *p_xh, *p_xl, *p_wqh, *p_wql, *p_wph, *p_wpl, *p_qh, *p_ql, *p_ah, *p_al, *p_bm;
    cudaGetSymbolAddress(&p_xh,  g_xh);
    cudaGetSymbolAddress(&p_xl,  g_xl);
    cudaGetSymbolAddress(&p_wqh, g_wqkvT_h);
    cudaGetSymbolAddress(&p_wql, g_wqkvT_l);
    cudaGetSymbolAddress(&p_wph, g_wprojT_h);
    cudaGetSymbolAddress(&p_wpl, g_wprojT_l);
    cudaGetSymbolAddress(&p_qh,  g_qkvh);
    cudaGetSymbolAddress(&p_ql,  g_qkvl);
    cudaGetSymbolAddress(&p_ah,  g_ah);
    cudaGetSymbolAddress(&p_al,  g_al);
    cudaGetSymbolAddress(&p_bm,  g_bias_m);

    cudaFuncSetAttribute(gemm3_kernel,
                         cudaFuncAttributeMaxDynamicSharedMemorySize, GEMM_SMEM);

    // (1) split x
    int n4 = (MTOT * DIMC) / 4;
    split_x_kernel<<<n4 / 256, 256>>>(x, (__nv_bfloat16*)p_xh, (__nv_bfloat16*)p_xl, n4);

    // (2) merged small prep
    prep_small_kernel<<<PREP_BM, 256>>>(w_qkv, w_proj, bias_table, rel_idx,
        (__nv_bfloat16*)p_wqh, (__nv_bfloat16*)p_wql,
        (__nv_bfloat16*)p_wph, (__nv_bfloat16*)p_wpl, (float*)p_bm);

    // (3) QKV GEMM -> split-bf16 qkv (q pre-scaled)
    gemm3_kernel<<<dim3(NQKV / 128, MTOT / 128), 256, GEMM_SMEM>>>(
        (const __nv_bfloat16*)p_xh, (const __nv_bfloat16*)p_xl,
        (const __nv_bfloat16*)p_wqh, (const __nv_bfloat16*)p_wql,
        nullptr, (__nv_bfloat16*)p_qh, (__nv_bfloat16*)p_ql, NQKV, nullptr);

    // (4) attention  <-- profiled slot
    attn_kernel<<<dim3(NH, MTOT / NW), 128, ATT_SMEM>>>(
        (const __nv_bfloat16*)p_qh, (const __nv_bfloat16*)p_ql,
        (const float*)p_bm, (__nv_bfloat16*)p_ah, (__nv_bfloat16*)p_al);

    // (5) proj GEMM + bias -> out (fp32)
    gemm3_kernel<<<dim3(DIMC / 128, MTOT / 128), 256, GEMM_SMEM>>>(
        (const __nv_bfloat16*)p_ah, (const __nv_bfloat16*)p_al,
        (const __nv_bfloat16*)p_wph, (const __nv_bfloat16*)p_wpl,
        out, nullptr, nullptr, DIMC, b_proj);
}

// round 13
// speedup vs baseline: 1.4357x; 1.4357x over previous
#include <cuda_runtime.h>
#include <cuda_fp16.h>
#include <cstdint>

// ============================================================================
// Swin window attention (quadratic norm), split-fp16 2-TERM HMMA pipeline:
//   A@B ~= (Ah+Al)@Bh  with A-side split to fp16 hi+lo (2^-22 exact),
//   B-side (weights / K / V) a single fp16 (dropped A*Bl ~ 1.7e-4 rms).
//   1) split_x (fp16 h+l); prep (w->fp16, bias matrix)
//   2) QKV GEMM (2-term) -> fp16 qkv (q: h+l, k/v: h only)
//   3) attention: HMMA 2-term, fragments in registers           [slot 4]
//   4) proj GEMM (2-term) + bias -> out (fp32)
// R12 fix: g_qkvl sized MTOT*NQKV (it is indexed with row stride NQKV; the
// R11 under-sized buffer + fake "pad symbol" caused the illegal access).
// ============================================================================

#define NW     49
#define DIMC   384
#define NH     12
#define HD     32
#define SCALEF 0.17677669529663687f
#define MTOT   200704            // 4096 * 49 = 784 * 256
#define NQKV   1152

// ---- scratch (device globals) -----------------------------------------------
__device__ __half g_xh[(size_t)MTOT * DIMC];
__device__ __half g_xl[(size_t)MTOT * DIMC];
__device__ __half g_wqkvT[NQKV * DIMC];
__device__ __half g_wprojT[DIMC * DIMC];
__device__ __half g_qkvh[(size_t)MTOT * NQKV];
__device__ __half g_qkvl[(size_t)MTOT * NQKV];   // full row stride; only q cols used
__device__ __half g_ah[(size_t)MTOT * DIMC];
__device__ __half g_al[(size_t)MTOT * DIMC];
__device__ float  g_bias_m[NH * NW * NW];        // bias[h][r][c]

// ---- helpers ------------------------------------------------------------------
__device__ __forceinline__ uint32_t smem_to_u32(const void* p) {
    uint32_t a;
    asm("{ .reg .u64 t; cvta.to.shared.u64 t, %1; cvt.u32.u64 %0, t; }"
        : "=r"(a) : "l"(p));
    return a;
}
__device__ __forceinline__ void ldsm_x4(uint32_t& r0, uint32_t& r1,
                                        uint32_t& r2, uint32_t& r3, uint32_t a) {
    asm volatile("ldmatrix.sync.aligned.m8n8.x4.shared.b16 {%0,%1,%2,%3}, [%4];"
                 : "=r"(r0), "=r"(r1), "=r"(r2), "=r"(r3) : "r"(a));
}
__device__ __forceinline__ void ldsm_x2(uint32_t& r0, uint32_t& r1, uint32_t a) {
    asm volatile("ldmatrix.sync.aligned.m8n8.x2.shared.b16 {%0,%1}, [%2];"
                 : "=r"(r0), "=r"(r1) : "r"(a));
}
__device__ __forceinline__ void ldsm_x4t(uint32_t& r0, uint32_t& r1,
                                         uint32_t& r2, uint32_t& r3, uint32_t a) {
    asm volatile("ldmatrix.sync.aligned.m8n8.x4.trans.shared.b16 {%0,%1,%2,%3}, [%4];"
                 : "=r"(r0), "=r"(r1), "=r"(r2), "=r"(r3) : "r"(a));
}
__device__ __forceinline__ void mma_f16(float* d, const uint32_t* a, const uint32_t* b) {
    asm volatile("mma.sync.aligned.m16n8k16.row.col.f32.f16.f16.f32 "
                 "{%0,%1,%2,%3}, {%4,%5,%6,%7}, {%8,%9}, {%0,%1,%2,%3};"
                 : "+f"(d[0]), "+f"(d[1]), "+f"(d[2]), "+f"(d[3])
                 : "r"(a[0]), "r"(a[1]), "r"(a[2]), "r"(a[3]), "r"(b[0]), "r"(b[1]));
}
__device__ __forceinline__ void cp16(uint32_t dst, const void* src) {
    asm volatile("cp.async.cg.shared.global [%0], [%1], 16;" :: "r"(dst), "l"(src));
}
#define CP_COMMIT() asm volatile("cp.async.commit_group;" ::: "memory")
#define CP_WAIT(n)  asm volatile("cp.async.wait_group %0;" :: "n"(n) : "memory")

__device__ __forceinline__ void split2h(float v, __half& h, __half& l) {
    h = __float2half_rn(v);
    l = __float2half_rn(v - __half2float(h));
}
__device__ __forceinline__ void pack_split_h(float a, float b, uint32_t& ph, uint32_t& pl) {
    __half ha, la, hb, lb;
    split2h(a, ha, la); split2h(b, hb, lb);
    __half2 vh = { ha, hb }, vl = { la, lb };
    ph = *(uint32_t*)&vh;
    pl = *(uint32_t*)&vl;
}

// ============================================================================
// Kernel 1: split x (fp32 -> fp16 hi/lo)
// ============================================================================
__global__ void split_x_kernel(const float* __restrict__ x,
                               __half* __restrict__ xh,
                               __half* __restrict__ xl, int n4) {
    int i = blockIdx.x * 256 + threadIdx.x;
    if (i >= n4) return;
    float4 v = ((const float4*)x)[i];
    __half h0, h1, h2, h3, l0, l1, l2, l3;
    split2h(v.x, h0, l0); split2h(v.y, h1, l1);
    split2h(v.z, h2, l2); split2h(v.w, h3, l3);
    ushort4 hv = { __half_as_ushort(h0), __half_as_ushort(h1),
                   __half_as_ushort(h2), __half_as_ushort(h3) };
    ushort4 lv = { __half_as_ushort(l0), __half_as_ushort(l1),
                   __half_as_ushort(l2), __half_as_ushort(l3) };
    ((ushort4*)xh)[i] = hv;
    ((ushort4*)xl)[i] = lv;
}

// ============================================================================
// Kernel 2: prep — w transposes to single fp16, bias matrix
// ============================================================================
#define PREP_WQ 1728
#define PREP_WP (PREP_WQ + 576)
#define PREP_BM (PREP_WP + 113)

__global__ void prep_small_kernel(const float* __restrict__ wqkv,
                                  const float* __restrict__ wproj,
                                  const float* __restrict__ bt,
                                  const int* __restrict__ rel,
                                  __half* __restrict__ wq,
                                  __half* __restrict__ wp,
                                  float* __restrict__ bm) {
    int b = blockIdx.x;
    if (b < PREP_WQ) {
        int i = b * 256 + threadIdx.x;
        int n = i / DIMC, k = i - n * DIMC;
        wq[i] = __float2half_rn(wqkv[(size_t)k * NQKV + n]);
    } else if (b < PREP_WP) {
        int i = (b - PREP_WQ) * 256 + threadIdx.x;
        int n = i / DIMC, k = i - n * DIMC;
        wp[i] = __float2half_rn(wproj[(size_t)k * DIMC + n]);
    } else {
        int i = (b - PREP_WP) * 256 + threadIdx.x;
        if (i < NH * NW * NW) {
            int h = i / (NW * NW), idx = i - h * (NW * NW);
            bm[i] = bt[rel[idx] * NH + h];
        }
    }
}

// ============================================================================
// Kernel 3: split-fp16 2-TERM HMMA GEMM. CTA 256x128, 8 warps (64x64 warp
// tile), K-chunk 64, 2-stage cp.async. C = (Ah+Al) @ Bh.
// smem/stage: Ah(36864) Al(36864) Bh(18432) = 92160; x2 = 184320 B.
// Epilogues: Cf!=null -> fp32 (+bias); else fp16 Ch all cols (q cols scaled),
//            Cl only cols < 384 (q needs lo; k/v hi-only).
// ============================================================================
#define A_TILE_B 36864                 // 256 * 144
#define B_TILE_B 18432                 // 128 * 144
#define STAGE_B  (2 * A_TILE_B + B_TILE_B)   // 92160
#define GEMM_SMEM (2 * STAGE_B)              // 184320

__global__ void __launch_bounds__(256, 1)
gemm2_kernel(const __half* __restrict__ Ah,
             const __half* __restrict__ Al,
             const __half* __restrict__ Bh,
             float* __restrict__ Cf,
             __half* __restrict__ Ch,
             __half* __restrict__ Cl,
             int ldc,
             const float* __restrict__ bias) {
    extern __shared__ __align__(16) char smem[];
    const int tid  = threadIdx.x;
    const int warp = tid >> 5;
    const int lane = tid & 31;
    const uint32_t sb = smem_to_u32(smem);
    const int m0 = blockIdx.y * 256;
    const int n0 = blockIdx.x * 128;
    const int m_warp = (warp >> 1) * 64;   // 0,64,128,192
    const int n_warp = (warp & 1) * 64;    // 0,64

    float acc[4][8][4];
    #pragma unroll
    for (int mt = 0; mt < 4; ++mt)
        #pragma unroll
        for (int nt = 0; nt < 8; ++nt)
            #pragma unroll
            for (int e = 0; e < 4; ++e) acc[mt][nt][e] = 0.f;

    auto load_stage = [&](int stage, int ks) {
        const int k0 = ks * 64;
        const uint32_t base = sb + stage * STAGE_B;
        #pragma unroll
        for (int t = 0; t < 2; ++t) {          // Ah, Al: 2048 chunks each
            const char* src = (const char*)((t ? Al : Ah) + (size_t)m0 * DIMC + k0);
            uint32_t dst = base + t * A_TILE_B;
            #pragma unroll
            for (int i = 0; i < 8; ++i) {
                int u = tid + i * 256;
                int row = u >> 3, ch = u & 7;
                cp16(dst + row * 144 + ch * 16,
                     src + (size_t)row * (DIMC * 2) + ch * 16);
            }
        }
        {                                      // Bh: 1024 chunks
            const char* src = (const char*)(Bh + (size_t)n0 * DIMC + k0);
            uint32_t dst = base + 2 * A_TILE_B;
            #pragma unroll
            for (int i = 0; i < 4; ++i) {
                int u = tid + i * 256;
                int row = u >> 3, ch = u & 7;
                cp16(dst + row * 144 + ch * 16,
                     src + (size_t)row * (DIMC * 2) + ch * 16);
            }
        }
    };

    load_stage(0, 0);
    CP_COMMIT();

    const int NKS = DIMC / 64;   // 6
    for (int ks = 0; ks < NKS; ++ks) {
        const int s = ks & 1;
        __syncthreads();
        if (ks + 1 < NKS) {
            load_stage(1 - s, ks + 1);
            CP_COMMIT();
            CP_WAIT(1);
        } else {
            CP_WAIT(0);
        }
        __syncthreads();

        const uint32_t ahBase = sb + s * STAGE_B;
        const uint32_t alBase = ahBase + A_TILE_B;
        const uint32_t bhBase = ahBase + 2 * A_TILE_B;
        const int rB = lane & 7, jB = (lane >> 3) & 1;
        const int rA = lane & 7, jA8 = ((lane >> 3) & 1) * 8, kA16 = ((lane >> 4) & 1) * 16;

        #pragma unroll
        for (int kk = 0; kk < 4; ++kk) {
            uint32_t ah[4][4], al[4][4];
            #pragma unroll
            for (int mt = 0; mt < 4; ++mt) {
                uint32_t off = (uint32_t)(m_warp + mt * 16 + jA8 + rA) * 144 + kk * 32 + kA16;
                ldsm_x4(ah[mt][0], ah[mt][1], ah[mt][2], ah[mt][3], ahBase + off);
                ldsm_x4(al[mt][0], al[mt][1], al[mt][2], al[mt][3], alBase + off);
            }
            uint32_t bh[8][2];
            #pragma unroll
            for (int nt = 0; nt < 8; ++nt) {
                uint32_t off = (uint32_t)(n_warp + nt * 8 + rB) * 144 + kk * 32 + jB * 16;
                ldsm_x2(bh[nt][0], bh[nt][1], bhBase + off);
            }
            // term-outer: same-accumulator MMAs are 32 apart
            #pragma unroll
            for (int mt = 0; mt < 4; ++mt)
                #pragma unroll
                for (int nt = 0; nt < 8; ++nt)
                    mma_f16(acc[mt][nt], ah[mt], bh[nt]);
            #pragma unroll
            for (int mt = 0; mt < 4; ++mt)
                #pragma unroll
                for (int nt = 0; nt < 8; ++nt)
                    mma_f16(acc[mt][nt], al[mt], bh[nt]);
        }
    }

    const int mrow  = m0 + m_warp + (lane >> 2);
    const int ncol0 = n0 + n_warp + (lane & 3) * 2;
    if (Cf) {
        #pragma unroll
        for (int mt = 0; mt < 4; ++mt) {
            #pragma unroll
            for (int nt = 0; nt < 8; ++nt) {
                int m = mrow + mt * 16;
                int n = ncol0 + nt * 8;
                float2 v0 = { acc[mt][nt][0], acc[mt][nt][1] };
                float2 v1 = { acc[mt][nt][2], acc[mt][nt][3] };
                if (bias) {
                    float2 bv = *(const float2*)&bias[n];
                    v0.x += bv.x; v0.y += bv.y; v1.x += bv.x; v1.y += bv.y;
                }
                *(float2*)&Cf[(size_t)m * ldc + n]       = v0;
                *(float2*)&Cf[(size_t)(m + 8) * ldc + n] = v1;
            }
        }
    } else {
        #pragma unroll
        for (int mt = 0; mt < 4; ++mt) {
            #pragma unroll
            for (int nt = 0; nt < 8; ++nt) {
                int m = mrow + mt * 16;
                int n = ncol0 + nt * 8;
                bool isq = (n < DIMC);
                float sc = isq ? SCALEF : 1.0f;   // q columns pre-scaled
                uint32_t ph, pl;
                pack_split_h(acc[mt][nt][0] * sc, acc[mt][nt][1] * sc, ph, pl);
                *(uint32_t*)&Ch[(size_t)m * ldc + n] = ph;
                if (isq) *(uint32_t*)&Cl[(size_t)m * ldc + n] = pl;
                pack_split_h(acc[mt][nt][2] * sc, acc[mt][nt][3] * sc, ph, pl);
                *(uint32_t*)&Ch[(size_t)(m + 8) * ldc + n] = ph;
                if (isq) *(uint32_t*)&Cl[(size_t)(m + 8) * ldc + n] = pl;
            }
        }
    }
}

// ============================================================================
// Kernel 4: HMMA attention, 2-term fp16. One CTA per (window, head), 128 thr.
// smem (20 KB): Qh@0 Ql@5120 Kh@10240 Vh@15360 (64 rows x 80B).
// S = (Qh+Ql) Kh; A^2 split in registers; O = (A2h+A2l) Vh (ldsm.trans).
// ============================================================================
#define ATT_SMEM 20480

__global__ void __launch_bounds__(128, 5)
attn_kernel(const __half* __restrict__ qkvh,
            const __half* __restrict__ qkvl,
            const float* __restrict__ bias_m,
            __half* __restrict__ oh,
            __half* __restrict__ ol) {
    extern __shared__ __align__(16) char smem[];
    const uint32_t sb = smem_to_u32(smem);

    const int tid  = threadIdx.x;
    const int warp = tid >> 5;
    const int lane = tid & 31;
    const int head = blockIdx.x;
    const size_t base = (size_t)blockIdx.y * NW;
    const float* bmh = bias_m + head * (NW * NW);

    // ---- zero V pad rows 49-63 (75 uint4) ----
    {
        uint4 z = {0, 0, 0, 0};
        for (int i = tid; i < 75; i += 128) {
            int rr = i / 5, cc = i % 5;
            *(uint4*)(smem + 15360 + (49 + rr) * 80 + cc * 16) = z;
        }
    }

    // ---- copy qh/ql/kh/vh: 784 x 16B chunks ----
    #pragma unroll
    for (int it = 0; it < 7; ++it) {
        int c = tid + it * 128;
        if (c < NW * 16) {
            int r = c / 16, rem = c & 15;
            int arr = rem >> 2, ch = rem & 3;      // 0:qh 1:ql 2:kh 3:vh
            const __half* src = (arr == 1) ? qkvl : qkvh;
            int seg = (arr < 2) ? 0 : (arr == 2 ? 1 : 2);
            const char* s = (const char*)(src + (base + r) * NQKV + seg * DIMC
                                          + head * HD) + ch * 16;
            *(uint4*)(smem + (uint32_t)arr * 5120u + r * 80 + ch * 16) = *(const uint4*)s;
        }
    }
    __syncthreads();

    const int rA = lane & 7, jA8 = ((lane >> 3) & 1) * 8, kA16 = ((lane >> 4) & 1) * 16;
    const int rB4 = (lane & 7) + ((lane >> 4) << 3);
    const int kB16 = ((lane >> 3) & 1) * 16;

    // ---- phase 1: S = (Qh+Ql) Kh  (M=16/warp, N=56, K=32) ----
    float s[7][4];
    #pragma unroll
    for (int j = 0; j < 7; ++j)
        #pragma unroll
        for (int e = 0; e < 4; ++e) s[j][e] = 0.f;

    #pragma unroll
    for (int kk = 0; kk < 2; ++kk) {
        uint32_t offA = (uint32_t)(16 * warp + jA8 + rA) * 80 + kk * 32 + kA16;
        uint32_t qh[4], ql[4];
        ldsm_x4(qh[0], qh[1], qh[2], qh[3], sb + offA);
        ldsm_x4(ql[0], ql[1], ql[2], ql[3], sb + 5120 + offA);
        uint32_t kh[7][2];
        #pragma unroll
        for (int p = 0; p < 3; ++p) {
            uint32_t off = (uint32_t)(16 * p + rB4) * 80 + kk * 32 + kB16;
            ldsm_x4(kh[2*p][0], kh[2*p][1], kh[2*p+1][0], kh[2*p+1][1], sb + 10240 + off);
        }
        {
            uint32_t off = (uint32_t)(48 + (lane & 7)) * 80 + kk * 32
                           + ((lane >> 3) & 1) * 16;
            ldsm_x2(kh[6][0], kh[6][1], sb + 10240 + off);
        }
        #pragma unroll
        for (int j = 0; j < 7; ++j) mma_f16(s[j], qh, kh[j]);
        #pragma unroll
        for (int j = 0; j < 7; ++j) mma_f16(s[j], ql, kh[j]);
    }

    // ---- phase 2 (registers): bias + square -> packed fp16 A frags + rowsum ----
    const int qd = lane >> 2;
    const int e2 = (lane & 3) * 2;
    const int r0 = 16 * warp + qd;
    const int r1 = r0 + 8;
    const bool r0v = (r0 < NW), r1v = (r1 < NW);
    uint32_t ah_t[4][4], al_t[4][4];
    float sum0 = 0.f, sum1 = 0.f;
    #pragma unroll
    for (int j = 0; j < 7; ++j) {
        int c = j * 8 + e2;
        bool c0v = (c < NW), c1v = (c + 1 < NW);
        float a00 = 0.f, a01 = 0.f, a10 = 0.f, a11 = 0.f;
        if (r0v && c0v) { float t = s[j][0] + __ldg(bmh + r0 * NW + c);     a00 = t * t; }
        if (r0v && c1v) { float t = s[j][1] + __ldg(bmh + r0 * NW + c + 1); a01 = t * t; }
        if (r1v && c0v) { float t = s[j][2] + __ldg(bmh + r1 * NW + c);     a10 = t * t; }
        if (r1v && c1v) { float t = s[j][3] + __ldg(bmh + r1 * NW + c + 1); a11 = t * t; }
        sum0 += a00 + a01;
        sum1 += a10 + a11;
        int t = j >> 1, hbase = (j & 1) * 2;
        pack_split_h(a00, a01, ah_t[t][hbase + 0], al_t[t][hbase + 0]);
        pack_split_h(a10, a11, ah_t[t][hbase + 1], al_t[t][hbase + 1]);
    }
    ah_t[3][2] = 0u; ah_t[3][3] = 0u;     // j = 7 zero band
    al_t[3][2] = 0u; al_t[3][3] = 0u;
    sum0 += __shfl_xor_sync(0xFFFFFFFFu, sum0, 1);
    sum0 += __shfl_xor_sync(0xFFFFFFFFu, sum0, 2);
    sum1 += __shfl_xor_sync(0xFFFFFFFFu, sum1, 1);
    sum1 += __shfl_xor_sync(0xFFFFFFFFu, sum1, 2);
    const float rs0 = 1.0f / (sum0 + 1e-6f);
    const float rs1 = 1.0f / (sum1 + 1e-6f);

    // ---- phase 3: O = (A2h+A2l) Vh  (M=16/warp, N=32, K=64) ----
    float o[4][4];
    #pragma unroll
    for (int n = 0; n < 4; ++n)
        #pragma unroll
        for (int e = 0; e < 4; ++e) o[n][e] = 0.f;

    #pragma unroll
    for (int kk = 0; kk < 4; ++kk) {
        int kv = kk * 16 + ((lane >> 3) & 1) * 8 + (lane & 7);
        uint32_t off0 = (uint32_t)kv * 80 + ((lane >> 4) * 8) * 2;
        uint32_t off1 = off0 + 32;
        uint32_t vh[4][2];
        ldsm_x4t(vh[0][0], vh[0][1], vh[1][0], vh[1][1], sb + 15360 + off0);
        ldsm_x4t(vh[2][0], vh[2][1], vh[3][0], vh[3][1], sb + 15360 + off1);
        #pragma unroll
        for (int n = 0; n < 4; ++n) mma_f16(o[n], ah_t[kk], vh[n]);
        #pragma unroll
        for (int n = 0; n < 4; ++n) mma_f16(o[n], al_t[kk], vh[n]);
    }

    // ---- phase 4: normalize + split-fp16 store (h+l, A-side of proj) ----
    #pragma unroll
    for (int n = 0; n < 4; ++n) {
        int d = n * 8 + e2;
        if (r0v) {
            uint32_t ph, pl;
            pack_split_h(o[n][0] * rs0, o[n][1] * rs0, ph, pl);
            size_t oi = (base + r0) * DIMC + head * HD + d;
            *(uint32_t*)&oh[oi] = ph;
            *(uint32_t*)&ol[oi] = pl;
        }
        if (r1v) {
            uint32_t ph, pl;
            pack_split_h(o[n][2] * rs1, o[n][3] * rs1, ph, pl);
            size_t oi = (base + r1) * DIMC + head * HD + d;
            *(uint32_t*)&oh[oi] = ph;
            *(uint32_t*)&ol[oi] = pl;
        }
    }
}

// ============================================================================
// launch — attn stays the 4th launch (profiled slot)
// ============================================================================
extern "C" void kernel_launch(void* const* d_in, const int* in_sizes, int n_in,
                              void* d_out, int out_size) {
    const float* x          = (const float*)d_in[0];
    const float* w_qkv      = (const float*)d_in[1];
    const float* w_proj     = (const float*)d_in[2];
    const float* b_proj     = (const float*)d_in[3];
    const float* bias_table = (const float*)d_in[4];
    const int*   rel_idx    = (const int*)d_in[5];
    float* out = (float*)d_out;

    void *p_xh, *p_xl, *p_wq, *p_wp, *p_qh, *p_ql, *p_ah, *p_al, *p_bm;
    cudaGetSymbolAddress(&p_xh, g_xh);
    cudaGetSymbolAddress(&p_xl, g_xl);
    cudaGetSymbolAddress(&p_wq, g_wqkvT);
    cudaGetSymbolAddress(&p_wp, g_wprojT);
    cudaGetSymbolAddress(&p_qh, g_qkvh);
    cudaGetSymbolAddress(&p_ql, g_qkvl);
    cudaGetSymbolAddress(&p_ah, g_ah);
    cudaGetSymbolAddress(&p_al, g_al);
    cudaGetSymbolAddress(&p_bm, g_bias_m);

    cudaFuncSetAttribute(gemm2_kernel,
                         cudaFuncAttributeMaxDynamicSharedMemorySize, GEMM_SMEM);

    // (1) split x -> fp16 h+l
    int n4 = (MTOT * DIMC) / 4;
    split_x_kernel<<<n4 / 256, 256>>>(x, (__half*)p_xh, (__half*)p_xl, n4);

    // (2) prep: weights -> fp16 (transposed), bias matrix
    prep_small_kernel<<<PREP_BM, 256>>>(w_qkv, w_proj, bias_table, rel_idx,
        (__half*)p_wq, (__half*)p_wp, (float*)p_bm);

    // (3) QKV GEMM (2-term) -> fp16 qkv (q pre-scaled, lo only for q cols)
    gemm2_kernel<<<dim3(NQKV / 128, MTOT / 256), 256, GEMM_SMEM>>>(
        (const __half*)p_xh, (const __half*)p_xl, (const __half*)p_wq,
        nullptr, (__half*)p_qh, (__half*)p_ql, NQKV, nullptr);

    // (4) attention  <-- profiled slot
    attn_kernel<<<dim3(NH, MTOT / NW), 128, ATT_SMEM>>>(
        (const __half*)p_qh, (const __half*)p_ql,
        (const float*)p_bm, (__half*)p_ah, (__half*)p_al);

    // (5) proj GEMM (2-term) + bias -> out (fp32)
    gemm2_kernel<<<dim3(DIMC / 128, MTOT / 256), 256, GEMM_SMEM>>>(
        (const __half*)p_ah, (const __half*)p_al, (const __half*)p_wp,
        out, nullptr, nullptr, DIMC, b_proj);
}

// round 14
// speedup vs baseline: 1.6475x; 1.1475x over previous
#include <cuda_runtime.h>
#include <cuda_fp16.h>
#include <cstdint>

// ============================================================================
// Swin window attention (quadratic norm), split-fp16 HMMA pipeline:
//   q columns: 2-term (xh+xl)@W;  k/v columns: 1-term xh@W (their outputs are
//   single-fp16 anyway, so the lo correction is below output rounding).
//   1) split_x; prep_w; prep_bias (fragment-layout bias)
//   2) QKV GEMM  [slot 4: profiled]
//   3) attention (HMMA, register A fragments, coalesced frag bias)
//   4) proj GEMM (2-term) + bias -> out (fp32)
// ============================================================================

#define NW     49
#define DIMC   384
#define NH     12
#define HD     32
#define SCALEF 0.17677669529663687f
#define MTOT   200704            // 4096 * 49 = 784 * 256
#define NQKV   1152

// ---- scratch (device globals) -----------------------------------------------
__device__ __half g_xh[(size_t)MTOT * DIMC];
__device__ __half g_xl[(size_t)MTOT * DIMC];
__device__ __half g_wqkvT[NQKV * DIMC];
__device__ __half g_wprojT[DIMC * DIMC];
__device__ __half g_qkvh[(size_t)MTOT * NQKV];
__device__ __half g_qkvl[(size_t)MTOT * NQKV];   // full row stride; only q cols used
__device__ __half g_ah[(size_t)MTOT * DIMC];
__device__ __half g_al[(size_t)MTOT * DIMC];
__device__ float4 g_bias_frag[NH * 4 * 7 * 32];  // [h][warp][j][lane] -> 4 vals

// ---- helpers ------------------------------------------------------------------
__device__ __forceinline__ uint32_t smem_to_u32(const void* p) {
    uint32_t a;
    asm("{ .reg .u64 t; cvta.to.shared.u64 t, %1; cvt.u32.u64 %0, t; }"
        : "=r"(a) : "l"(p));
    return a;
}
__device__ __forceinline__ void ldsm_x4(uint32_t& r0, uint32_t& r1,
                                        uint32_t& r2, uint32_t& r3, uint32_t a) {
    asm volatile("ldmatrix.sync.aligned.m8n8.x4.shared.b16 {%0,%1,%2,%3}, [%4];"
                 : "=r"(r0), "=r"(r1), "=r"(r2), "=r"(r3) : "r"(a));
}
__device__ __forceinline__ void ldsm_x2(uint32_t& r0, uint32_t& r1, uint32_t a) {
    asm volatile("ldmatrix.sync.aligned.m8n8.x2.shared.b16 {%0,%1}, [%2];"
                 : "=r"(r0), "=r"(r1) : "r"(a));
}
__device__ __forceinline__ void ldsm_x4t(uint32_t& r0, uint32_t& r1,
                                         uint32_t& r2, uint32_t& r3, uint32_t a) {
    asm volatile("ldmatrix.sync.aligned.m8n8.x4.trans.shared.b16 {%0,%1,%2,%3}, [%4];"
                 : "=r"(r0), "=r"(r1), "=r"(r2), "=r"(r3) : "r"(a));
}
__device__ __forceinline__ void mma_f16(float* d, const uint32_t* a, const uint32_t* b) {
    asm volatile("mma.sync.aligned.m16n8k16.row.col.f32.f16.f16.f32 "
                 "{%0,%1,%2,%3}, {%4,%5,%6,%7}, {%8,%9}, {%0,%1,%2,%3};"
                 : "+f"(d[0]), "+f"(d[1]), "+f"(d[2]), "+f"(d[3])
                 : "r"(a[0]), "r"(a[1]), "r"(a[2]), "r"(a[3]), "r"(b[0]), "r"(b[1]));
}
__device__ __forceinline__ void cp16(uint32_t dst, const void* src) {
    asm volatile("cp.async.cg.shared.global [%0], [%1], 16;" :: "r"(dst), "l"(src));
}
#define CP_COMMIT() asm volatile("cp.async.commit_group;" ::: "memory")
#define CP_WAIT(n)  asm volatile("cp.async.wait_group %0;" :: "n"(n) : "memory")

__device__ __forceinline__ void split2h(float v, __half& h, __half& l) {
    h = __float2half_rn(v);
    l = __float2half_rn(v - __half2float(h));
}
__device__ __forceinline__ void pack_split_h(float a, float b, uint32_t& ph, uint32_t& pl) {
    __half ha, la, hb, lb;
    split2h(a, ha, la); split2h(b, hb, lb);
    __half2 vh = { ha, hb }, vl = { la, lb };
    ph = *(uint32_t*)&vh;
    pl = *(uint32_t*)&vl;
}

// ============================================================================
// Kernel 1: split x (fp32 -> fp16 hi/lo)
// ============================================================================
__global__ void split_x_kernel(const float* __restrict__ x,
                               __half* __restrict__ xh,
                               __half* __restrict__ xl, int n4) {
    int i = blockIdx.x * 256 + threadIdx.x;
    if (i >= n4) return;
    float4 v = ((const float4*)x)[i];
    __half h0, h1, h2, h3, l0, l1, l2, l3;
    split2h(v.x, h0, l0); split2h(v.y, h1, l1);
    split2h(v.z, h2, l2); split2h(v.w, h3, l3);
    ushort4 hv = { __half_as_ushort(h0), __half_as_ushort(h1),
                   __half_as_ushort(h2), __half_as_ushort(h3) };
    ushort4 lv = { __half_as_ushort(l0), __half_as_ushort(l1),
                   __half_as_ushort(l2), __half_as_ushort(l3) };
    ((ushort4*)xh)[i] = hv;
    ((ushort4*)xl)[i] = lv;
}

// ============================================================================
// Kernel 2a: weights -> fp16 transposed
// ============================================================================
#define PREP_WQ 1728
#define PREP_WP (PREP_WQ + 576)

__global__ void prep_w_kernel(const float* __restrict__ wqkv,
                              const float* __restrict__ wproj,
                              __half* __restrict__ wq,
                              __half* __restrict__ wp) {
    int b = blockIdx.x;
    if (b < PREP_WQ) {
        int i = b * 256 + threadIdx.x;
        int n = i / DIMC, k = i - n * DIMC;
        wq[i] = __float2half_rn(wqkv[(size_t)k * NQKV + n]);
    } else {
        int i = (b - PREP_WQ) * 256 + threadIdx.x;
        int n = i / DIMC, k = i - n * DIMC;
        wp[i] = __float2half_rn(wproj[(size_t)k * DIMC + n]);
    }
}

// ============================================================================
// Kernel 2b: bias in attn fragment layout: [h][warp][j][lane] float4 =
//   { b(r0,c), b(r0,c+1), b(r1,c), b(r1,c+1) }, zeros outside 49x49.
// ============================================================================
__global__ void prep_bias_kernel(const float* __restrict__ bt,
                                 const int* __restrict__ rel,
                                 float4* __restrict__ bmf) {
    int i = blockIdx.x * 256 + threadIdx.x;
    if (i >= NH * 4 * 7 * 32) return;
    int lane = i & 31;
    int j = (i >> 5) % 7;
    int w = (i / (32 * 7)) % 4;
    int h = i / (32 * 7 * 4);
    int qd = lane >> 2, e2 = (lane & 3) * 2;
    int r0 = 16 * w + qd, r1 = r0 + 8;
    int c = 8 * j + e2;
    float4 v = { 0.f, 0.f, 0.f, 0.f };
    if (r0 < NW && c < NW)     v.x = bt[rel[r0 * NW + c] * NH + h];
    if (r0 < NW && c + 1 < NW) v.y = bt[rel[r0 * NW + c + 1] * NH + h];
    if (r1 < NW && c < NW)     v.z = bt[rel[r1 * NW + c] * NH + h];
    if (r1 < NW && c + 1 < NW) v.w = bt[rel[r1 * NW + c + 1] * NH + h];
    bmf[i] = v;
}

// ============================================================================
// Kernel 3: split-fp16 HMMA GEMM. CTA 256x128, 8 warps (64x64 warp tile),
// K-chunk 64, 2-stage cp.async.
//   two_term = (n0 < 384): q columns (and all of proj) use (Ah+Al)@Bh;
//   k/v column blocks use 1-term Ah@Bh (skip Al load + MMAs).
// ============================================================================
#define A_TILE_B 36864                 // 256 * 144
#define B_TILE_B 18432                 // 128 * 144
#define STAGE_B  (2 * A_TILE_B + B_TILE_B)   // 92160
#define GEMM_SMEM (2 * STAGE_B)              // 184320

__global__ void __launch_bounds__(256, 1)
gemm2_kernel(const __half* __restrict__ Ah,
             const __half* __restrict__ Al,
             const __half* __restrict__ Bh,
             float* __restrict__ Cf,
             __half* __restrict__ Ch,
             __half* __restrict__ Cl,
             int ldc,
             const float* __restrict__ bias) {
    extern __shared__ __align__(16) char smem[];
    const int tid  = threadIdx.x;
    const int warp = tid >> 5;
    const int lane = tid & 31;
    const uint32_t sb = smem_to_u32(smem);
    const int m0 = blockIdx.y * 256;
    const int n0 = blockIdx.x * 128;
    const int m_warp = (warp >> 1) * 64;   // 0,64,128,192
    const int n_warp = (warp & 1) * 64;    // 0,64
    const bool two_term = (n0 < DIMC);

    float acc[4][8][4];
    #pragma unroll
    for (int mt = 0; mt < 4; ++mt)
        #pragma unroll
        for (int nt = 0; nt < 8; ++nt)
            #pragma unroll
            for (int e = 0; e < 4; ++e) acc[mt][nt][e] = 0.f;

    auto load_stage = [&](int stage, int ks) {
        const int k0 = ks * 64;
        const uint32_t base = sb + stage * STAGE_B;
        {                                      // Ah: 2048 chunks
            const char* src = (const char*)(Ah + (size_t)m0 * DIMC + k0);
            #pragma unroll
            for (int i = 0; i < 8; ++i) {
                int u = tid + i * 256;
                int row = u >> 3, ch = u & 7;
                cp16(base + row * 144 + ch * 16,
                     src + (size_t)row * (DIMC * 2) + ch * 16);
            }
        }
        if (two_term) {                        // Al: 2048 chunks
            const char* src = (const char*)(Al + (size_t)m0 * DIMC + k0);
            uint32_t dst = base + A_TILE_B;
            #pragma unroll
            for (int i = 0; i < 8; ++i) {
                int u = tid + i * 256;
                int row = u >> 3, ch = u & 7;
                cp16(dst + row * 144 + ch * 16,
                     src + (size_t)row * (DIMC * 2) + ch * 16);
            }
        }
        {                                      // Bh: 1024 chunks
            const char* src = (const char*)(Bh + (size_t)n0 * DIMC + k0);
            uint32_t dst = base + 2 * A_TILE_B;
            #pragma unroll
            for (int i = 0; i < 4; ++i) {
                int u = tid + i * 256;
                int row = u >> 3, ch = u & 7;
                cp16(dst + row * 144 + ch * 16,
                     src + (size_t)row * (DIMC * 2) + ch * 16);
            }
        }
    };

    load_stage(0, 0);
    CP_COMMIT();

    const int NKS = DIMC / 64;   // 6
    for (int ks = 0; ks < NKS; ++ks) {
        const int s = ks & 1;
        __syncthreads();
        if (ks + 1 < NKS) {
            load_stage(1 - s, ks + 1);
            CP_COMMIT();
            CP_WAIT(1);
        } else {
            CP_WAIT(0);
        }
        __syncthreads();

        const uint32_t ahBase = sb + s * STAGE_B;
        const uint32_t alBase = ahBase + A_TILE_B;
        const uint32_t bhBase = ahBase + 2 * A_TILE_B;
        const int rB = lane & 7, jB = (lane >> 3) & 1;
        const int rA = lane & 7, jA8 = ((lane >> 3) & 1) * 8, kA16 = ((lane >> 4) & 1) * 16;

        #pragma unroll
        for (int kk = 0; kk < 4; ++kk) {
            uint32_t ah[4][4];
            #pragma unroll
            for (int mt = 0; mt < 4; ++mt) {
                uint32_t off = (uint32_t)(m_warp + mt * 16 + jA8 + rA) * 144 + kk * 32 + kA16;
                ldsm_x4(ah[mt][0], ah[mt][1], ah[mt][2], ah[mt][3], ahBase + off);
            }
            uint32_t bh[8][2];
            #pragma unroll
            for (int nt = 0; nt < 8; ++nt) {
                uint32_t off = (uint32_t)(n_warp + nt * 8 + rB) * 144 + kk * 32 + jB * 16;
                ldsm_x2(bh[nt][0], bh[nt][1], bhBase + off);
            }
            #pragma unroll
            for (int mt = 0; mt < 4; ++mt)
                #pragma unroll
                for (int nt = 0; nt < 8; ++nt)
                    mma_f16(acc[mt][nt], ah[mt], bh[nt]);
            if (two_term) {
                uint32_t al[4][4];
                #pragma unroll
                for (int mt = 0; mt < 4; ++mt) {
                    uint32_t off = (uint32_t)(m_warp + mt * 16 + jA8 + rA) * 144 + kk * 32 + kA16;
                    ldsm_x4(al[mt][0], al[mt][1], al[mt][2], al[mt][3], alBase + off);
                }
                #pragma unroll
                for (int mt = 0; mt < 4; ++mt)
                    #pragma unroll
                    for (int nt = 0; nt < 8; ++nt)
                        mma_f16(acc[mt][nt], al[mt], bh[nt]);
            }
        }
    }

    const int mrow  = m0 + m_warp + (lane >> 2);
    const int ncol0 = n0 + n_warp + (lane & 3) * 2;
    if (Cf) {
        #pragma unroll
        for (int mt = 0; mt < 4; ++mt) {
            #pragma unroll
            for (int nt = 0; nt < 8; ++nt) {
                int m = mrow + mt * 16;
                int n = ncol0 + nt * 8;
                float2 v0 = { acc[mt][nt][0], acc[mt][nt][1] };
                float2 v1 = { acc[mt][nt][2], acc[mt][nt][3] };
                if (bias) {
                    float2 bv = *(const float2*)&bias[n];
                    v0.x += bv.x; v0.y += bv.y; v1.x += bv.x; v1.y += bv.y;
                }
                *(float2*)&Cf[(size_t)m * ldc + n]       = v0;
                *(float2*)&Cf[(size_t)(m + 8) * ldc + n] = v1;
            }
        }
    } else {
        #pragma unroll
        for (int mt = 0; mt < 4; ++mt) {
            #pragma unroll
            for (int nt = 0; nt < 8; ++nt) {
                int m = mrow + mt * 16;
                int n = ncol0 + nt * 8;
                bool isq = (n < DIMC);
                float sc = isq ? SCALEF : 1.0f;   // q columns pre-scaled
                uint32_t ph, pl;
                pack_split_h(acc[mt][nt][0] * sc, acc[mt][nt][1] * sc, ph, pl);
                *(uint32_t*)&Ch[(size_t)m * ldc + n] = ph;
                if (isq) *(uint32_t*)&Cl[(size_t)m * ldc + n] = pl;
                pack_split_h(acc[mt][nt][2] * sc, acc[mt][nt][3] * sc, ph, pl);
                *(uint32_t*)&Ch[(size_t)(m + 8) * ldc + n] = ph;
                if (isq) *(uint32_t*)&Cl[(size_t)(m + 8) * ldc + n] = pl;
            }
        }
    }
}

// ============================================================================
// Kernel 4: HMMA attention, 2-term fp16, frag-layout bias (coalesced).
// smem (20 KB): Qh@0 Ql@5120 Kh@10240 Vh@15360 (64 rows x 80B).
// ============================================================================
#define ATT_SMEM 20480

__global__ void __launch_bounds__(128, 5)
attn_kernel(const __half* __restrict__ qkvh,
            const __half* __restrict__ qkvl,
            const float4* __restrict__ bias_frag,
            __half* __restrict__ oh,
            __half* __restrict__ ol) {
    extern __shared__ __align__(16) char smem[];
    const uint32_t sb = smem_to_u32(smem);

    const int tid  = threadIdx.x;
    const int warp = tid >> 5;
    const int lane = tid & 31;
    const int head = blockIdx.x;
    const size_t base = (size_t)blockIdx.y * NW;

    // ---- zero V pad rows 49-63 (75 uint4) ----
    {
        uint4 z = {0, 0, 0, 0};
        for (int i = tid; i < 75; i += 128) {
            int rr = i / 5, cc = i % 5;
            *(uint4*)(smem + 15360 + (49 + rr) * 80 + cc * 16) = z;
        }
    }

    // ---- copy qh/ql/kh/vh: 784 x 16B chunks ----
    #pragma unroll
    for (int it = 0; it < 7; ++it) {
        int c = tid + it * 128;
        if (c < NW * 16) {
            int r = c / 16, rem = c & 15;
            int arr = rem >> 2, ch = rem & 3;      // 0:qh 1:ql 2:kh 3:vh
            const __half* src = (arr == 1) ? qkvl : qkvh;
            int seg = (arr < 2) ? 0 : (arr == 2 ? 1 : 2);
            const char* s = (const char*)(src + (base + r) * NQKV + seg * DIMC
                                          + head * HD) + ch * 16;
            *(uint4*)(smem + (uint32_t)arr * 5120u + r * 80 + ch * 16) = *(const uint4*)s;
        }
    }
    __syncthreads();

    const int rA = lane & 7, jA8 = ((lane >> 3) & 1) * 8, kA16 = ((lane >> 4) & 1) * 16;
    const int rB4 = (lane & 7) + ((lane >> 4) << 3);
    const int kB16 = ((lane >> 3) & 1) * 16;

    // ---- phase 1: S = (Qh+Ql) Kh  (M=16/warp, N=56, K=32) ----
    float s[7][4];
    #pragma unroll
    for (int j = 0; j < 7; ++j)
        #pragma unroll
        for (int e = 0; e < 4; ++e) s[j][e] = 0.f;

    #pragma unroll
    for (int kk = 0; kk < 2; ++kk) {
        uint32_t offA = (uint32_t)(16 * warp + jA8 + rA) * 80 + kk * 32 + kA16;
        uint32_t qh[4], ql[4];
        ldsm_x4(qh[0], qh[1], qh[2], qh[3], sb + offA);
        ldsm_x4(ql[0], ql[1], ql[2], ql[3], sb + 5120 + offA);
        uint32_t kh[7][2];
        #pragma unroll
        for (int p = 0; p < 3; ++p) {
            uint32_t off = (uint32_t)(16 * p + rB4) * 80 + kk * 32 + kB16;
            ldsm_x4(kh[2*p][0], kh[2*p][1], kh[2*p+1][0], kh[2*p+1][1], sb + 10240 + off);
        }
        {
            uint32_t off = (uint32_t)(48 + (lane & 7)) * 80 + kk * 32
                           + ((lane >> 3) & 1) * 16;
            ldsm_x2(kh[6][0], kh[6][1], sb + 10240 + off);
        }
        #pragma unroll
        for (int j = 0; j < 7; ++j) mma_f16(s[j], qh, kh[j]);
        #pragma unroll
        for (int j = 0; j < 7; ++j) mma_f16(s[j], ql, kh[j]);
    }

    // ---- phase 2 (registers): frag bias + square -> packed fp16 A + rowsum ----
    const int qd = lane >> 2;
    const int e2 = (lane & 3) * 2;
    const int r0 = 16 * warp + qd;
    const int r1 = r0 + 8;
    const bool r0v = (r0 < NW), r1v = (r1 < NW);
    const float4* bmf = bias_frag + ((size_t)(head * 4 + warp) * 7) * 32 + lane;
    uint32_t ah_t[4][4], al_t[4][4];
    float sum0 = 0.f, sum1 = 0.f;
    #pragma unroll
    for (int j = 0; j < 7; ++j) {
        int c = j * 8 + e2;
        bool c0v = (c < NW), c1v = (c + 1 < NW);
        float4 bv = __ldg(&bmf[j * 32]);
        float a00 = 0.f, a01 = 0.f, a10 = 0.f, a11 = 0.f;
        if (r0v && c0v) { float t = s[j][0] + bv.x; a00 = t * t; }
        if (r0v && c1v) { float t = s[j][1] + bv.y; a01 = t * t; }
        if (r1v && c0v) { float t = s[j][2] + bv.z; a10 = t * t; }
        if (r1v && c1v) { float t = s[j][3] + bv.w; a11 = t * t; }
        sum0 += a00 + a01;
        sum1 += a10 + a11;
        int t = j >> 1, hbase = (j & 1) * 2;
        pack_split_h(a00, a01, ah_t[t][hbase + 0], al_t[t][hbase + 0]);
        pack_split_h(a10, a11, ah_t[t][hbase + 1], al_t[t][hbase + 1]);
    }
    ah_t[3][2] = 0u; ah_t[3][3] = 0u;     // j = 7 zero band
    al_t[3][2] = 0u; al_t[3][3] = 0u;
    sum0 += __shfl_xor_sync(0xFFFFFFFFu, sum0, 1);
    sum0 += __shfl_xor_sync(0xFFFFFFFFu, sum0, 2);
    sum1 += __shfl_xor_sync(0xFFFFFFFFu, sum1, 1);
    sum1 += __shfl_xor_sync(0xFFFFFFFFu, sum1, 2);
    const float rs0 = 1.0f / (sum0 + 1e-6f);
    const float rs1 = 1.0f / (sum1 + 1e-6f);

    // ---- phase 3: O = (A2h+A2l) Vh  (M=16/warp, N=32, K=64) ----
    float o[4][4];
    #pragma unroll
    for (int n = 0; n < 4; ++n)
        #pragma unroll
        for (int e = 0; e < 4; ++e) o[n][e] = 0.f;

    #pragma unroll
    for (int kk = 0; kk < 4; ++kk) {
        int kv = kk * 16 + ((lane >> 3) & 1) * 8 + (lane & 7);
        uint32_t off0 = (uint32_t)kv * 80 + ((lane >> 4) * 8) * 2;
        uint32_t off1 = off0 + 32;
        uint32_t vh[4][2];
        ldsm_x4t(vh[0][0], vh[0][1], vh[1][0], vh[1][1], sb + 15360 + off0);
        ldsm_x4t(vh[2][0], vh[2][1], vh[3][0], vh[3][1], sb + 15360 + off1);
        #pragma unroll
        for (int n = 0; n < 4; ++n) mma_f16(o[n], ah_t[kk], vh[n]);
        #pragma unroll
        for (int n = 0; n < 4; ++n) mma_f16(o[n], al_t[kk], vh[n]);
    }

    // ---- phase 4: normalize + split-fp16 store ----
    #pragma unroll
    for (int n = 0; n < 4; ++n) {
        int d = n * 8 + e2;
        if (r0v) {
            uint32_t ph, pl;
            pack_split_h(o[n][0] * rs0, o[n][1] * rs0, ph, pl);
            size_t oi = (base + r0) * DIMC + head * HD + d;
            *(uint32_t*)&oh[oi] = ph;
            *(uint32_t*)&ol[oi] = pl;
        }
        if (r1v) {
            uint32_t ph, pl;
            pack_split_h(o[n][2] * rs1, o[n][3] * rs1, ph, pl);
            size_t oi = (base + r1) * DIMC + head * HD + d;
            *(uint32_t*)&oh[oi] = ph;
            *(uint32_t*)&ol[oi] = pl;
        }
    }
}

// ============================================================================
// launch — QKV GEMM is the 4th launch (profiled slot this round)
// ============================================================================
extern "C" void kernel_launch(void* const* d_in, const int* in_sizes, int n_in,
                              void* d_out, int out_size) {
    const float* x          = (const float*)d_in[0];
    const float* w_qkv      = (const float*)d_in[1];
    const float* w_proj     = (const float*)d_in[2];
    const float* b_proj     = (const float*)d_in[3];
    const float* bias_table = (const float*)d_in[4];
    const int*   rel_idx    = (const int*)d_in[5];
    float* out = (float*)d_out;

    void *p_xh, *p_xl, *p_wq, *p_wp, *p_qh, *p_ql, *p_ah, *p_al, *p_bf;
    cudaGetSymbolAddress(&p_xh, g_xh);
    cudaGetSymbolAddress(&p_xl, g_xl);
    cudaGetSymbolAddress(&p_wq, g_wqkvT);
    cudaGetSymbolAddress(&p_wp, g_wprojT);
    cudaGetSymbolAddress(&p_qh, g_qkvh);
    cudaGetSymbolAddress(&p_ql, g_qkvl);
    cudaGetSymbolAddress(&p_ah, g_ah);
    cudaGetSymbolAddress(&p_al, g_al);
    cudaGetSymbolAddress(&p_bf, g_bias_frag);

    cudaFuncSetAttribute(gemm2_kernel,
                         cudaFuncAttributeMaxDynamicSharedMemorySize, GEMM_SMEM);

    // (1) split x -> fp16 h+l
    int n4 = (MTOT * DIMC) / 4;
    split_x_kernel<<<n4 / 256, 256>>>(x, (__half*)p_xh, (__half*)p_xl, n4);

    // (2) weights -> fp16 (transposed)
    prep_w_kernel<<<PREP_WP, 256>>>(w_qkv, w_proj, (__half*)p_wq, (__half*)p_wp);

    // (3) bias -> fragment layout
    prep_bias_kernel<<<(NH * 4 * 7 * 32 + 255) / 256, 256>>>(
        bias_table, rel_idx, (float4*)p_bf);

    // (4) QKV GEMM  <-- profiled slot (q cols 2-term, k/v cols 1-term)
    gemm2_kernel<<<dim3(NQKV / 128, MTOT / 256), 256, GEMM_SMEM>>>(
        (const __half*)p_xh, (const __half*)p_xl, (const __half*)p_wq,
        nullptr, (__half*)p_qh, (__half*)p_ql, NQKV, nullptr);

    // (5) attention
    attn_kernel<<<dim3(NH, MTOT / NW), 128, ATT_SMEM>>>(
        (const __half*)p_qh, (const __half*)p_ql,
        (const float4*)p_bf, (__half*)p_ah, (__half*)p_al);

    // (6) proj GEMM (2-term) + bias -> out (fp32)
    gemm2_kernel<<<dim3(DIMC / 128, MTOT / 256), 256, GEMM_SMEM>>>(
        (const __half*)p_ah, (const __half*)p_al, (const __half*)p_wp,
        out, nullptr, nullptr, DIMC, b_proj);
}

// round 15
// speedup vs baseline: 1.8768x; 1.1392x over previous
#include <cuda_runtime.h>
#include <cuda_fp16.h>
#include <cstdint>

// ============================================================================
// Swin window attention (quadratic norm), split-fp16 HMMA pipeline:
//   QKV: q cols 2-term (xh+xl)@W, k/v cols 1-term xh@W.
//   attention: HMMA, register A fragments, frag-layout bias; fp16 output.
//   proj: 1-term ah@Wp (attention-output fp16 rounding accepted, ~2.4e-4).
// Launch order: split_x, prep(w+bias), QKV, attn [slot 4], proj.
// ============================================================================

#define NW     49
#define DIMC   384
#define NH     12
#define HD     32
#define SCALEF 0.17677669529663687f
#define MTOT   200704            // 4096 * 49 = 784 * 256
#define NQKV   1152

// ---- scratch (device globals) -----------------------------------------------
__device__ __half g_xh[(size_t)MTOT * DIMC];
__device__ __half g_xl[(size_t)MTOT * DIMC];
__device__ __half g_wqkvT[NQKV * DIMC];
__device__ __half g_wprojT[DIMC * DIMC];
__device__ __half g_qkvh[(size_t)MTOT * NQKV];
__device__ __half g_qkvl[(size_t)MTOT * NQKV];   // full row stride; only q cols used
__device__ __half g_ah[(size_t)MTOT * DIMC];
__device__ float4 g_bias_frag[NH * 4 * 7 * 32];  // [h][warp][j][lane]

// ---- helpers ------------------------------------------------------------------
__device__ __forceinline__ uint32_t smem_to_u32(const void* p) {
    uint32_t a;
    asm("{ .reg .u64 t; cvta.to.shared.u64 t, %1; cvt.u32.u64 %0, t; }"
        : "=r"(a) : "l"(p));
    return a;
}
__device__ __forceinline__ void ldsm_x4(uint32_t& r0, uint32_t& r1,
                                        uint32_t& r2, uint32_t& r3, uint32_t a) {
    asm volatile("ldmatrix.sync.aligned.m8n8.x4.shared.b16 {%0,%1,%2,%3}, [%4];"
                 : "=r"(r0), "=r"(r1), "=r"(r2), "=r"(r3) : "r"(a));
}
__device__ __forceinline__ void ldsm_x2(uint32_t& r0, uint32_t& r1, uint32_t a) {
    asm volatile("ldmatrix.sync.aligned.m8n8.x2.shared.b16 {%0,%1}, [%2];"
                 : "=r"(r0), "=r"(r1) : "r"(a));
}
__device__ __forceinline__ void ldsm_x4t(uint32_t& r0, uint32_t& r1,
                                         uint32_t& r2, uint32_t& r3, uint32_t a) {
    asm volatile("ldmatrix.sync.aligned.m8n8.x4.trans.shared.b16 {%0,%1,%2,%3}, [%4];"
                 : "=r"(r0), "=r"(r1), "=r"(r2), "=r"(r3) : "r"(a));
}
__device__ __forceinline__ void mma_f16(float* d, const uint32_t* a, const uint32_t* b) {
    asm volatile("mma.sync.aligned.m16n8k16.row.col.f32.f16.f16.f32 "
                 "{%0,%1,%2,%3}, {%4,%5,%6,%7}, {%8,%9}, {%0,%1,%2,%3};"
                 : "+f"(d[0]), "+f"(d[1]), "+f"(d[2]), "+f"(d[3])
                 : "r"(a[0]), "r"(a[1]), "r"(a[2]), "r"(a[3]), "r"(b[0]), "r"(b[1]));
}
__device__ __forceinline__ void cp16(uint32_t dst, const void* src) {
    asm volatile("cp.async.cg.shared.global [%0], [%1], 16;" :: "r"(dst), "l"(src));
}
#define CP_COMMIT() asm volatile("cp.async.commit_group;" ::: "memory")
#define CP_WAIT(n)  asm volatile("cp.async.wait_group %0;" :: "n"(n) : "memory")

__device__ __forceinline__ void split2h(float v, __half& h, __half& l) {
    h = __float2half_rn(v);
    l = __float2half_rn(v - __half2float(h));
}
__device__ __forceinline__ void pack_split_h(float a, float b, uint32_t& ph, uint32_t& pl) {
    __half ha, la, hb, lb;
    split2h(a, ha, la); split2h(b, hb, lb);
    __half2 vh = { ha, hb }, vl = { la, lb };
    ph = *(uint32_t*)&vh;
    pl = *(uint32_t*)&vl;
}

// ============================================================================
// Kernel 1: split x (fp32 -> fp16 hi/lo)
// ============================================================================
__global__ void split_x_kernel(const float* __restrict__ x,
                               __half* __restrict__ xh,
                               __half* __restrict__ xl, int n4) {
    int i = blockIdx.x * 256 + threadIdx.x;
    if (i >= n4) return;
    float4 v = ((const float4*)x)[i];
    __half h0, h1, h2, h3, l0, l1, l2, l3;
    split2h(v.x, h0, l0); split2h(v.y, h1, l1);
    split2h(v.z, h2, l2); split2h(v.w, h3, l3);
    ushort4 hv = { __half_as_ushort(h0), __half_as_ushort(h1),
                   __half_as_ushort(h2), __half_as_ushort(h3) };
    ushort4 lv = { __half_as_ushort(l0), __half_as_ushort(l1),
                   __half_as_ushort(l2), __half_as_ushort(l3) };
    ((ushort4*)xh)[i] = hv;
    ((ushort4*)xl)[i] = lv;
}

// ============================================================================
// Kernel 2: prep — w -> fp16 transposed; bias -> fragment layout.
// blocks: [0,1728) wqkv | [1728,2304) wproj | [2304, 2304+42) bias frag
// ============================================================================
#define PREP_WQ 1728
#define PREP_WP (PREP_WQ + 576)
#define PREP_BF (PREP_WP + 42)          // 12*4*7*32 = 10752 -> 42 blocks

__global__ void prep_kernel(const float* __restrict__ wqkv,
                            const float* __restrict__ wproj,
                            const float* __restrict__ bt,
                            const int* __restrict__ rel,
                            __half* __restrict__ wq,
                            __half* __restrict__ wp,
                            float4* __restrict__ bmf) {
    int b = blockIdx.x;
    if (b < PREP_WQ) {
        int i = b * 256 + threadIdx.x;
        int n = i / DIMC, k = i - n * DIMC;
        wq[i] = __float2half_rn(wqkv[(size_t)k * NQKV + n]);
    } else if (b < PREP_WP) {
        int i = (b - PREP_WQ) * 256 + threadIdx.x;
        int n = i / DIMC, k = i - n * DIMC;
        wp[i] = __float2half_rn(wproj[(size_t)k * DIMC + n]);
    } else {
        int i = (b - PREP_WP) * 256 + threadIdx.x;
        if (i < NH * 4 * 7 * 32) {
            int lane = i & 31;
            int j = (i >> 5) % 7;
            int w = (i / (32 * 7)) % 4;
            int h = i / (32 * 7 * 4);
            int qd = lane >> 2, e2 = (lane & 3) * 2;
            int r0 = 16 * w + qd, r1 = r0 + 8;
            int c = 8 * j + e2;
            float4 v = { 0.f, 0.f, 0.f, 0.f };
            if (r0 < NW && c < NW)     v.x = bt[rel[r0 * NW + c] * NH + h];
            if (r0 < NW && c + 1 < NW) v.y = bt[rel[r0 * NW + c + 1] * NH + h];
            if (r1 < NW && c < NW)     v.z = bt[rel[r1 * NW + c] * NH + h];
            if (r1 < NW && c + 1 < NW) v.w = bt[rel[r1 * NW + c + 1] * NH + h];
            bmf[i] = v;
        }
    }
}

// ============================================================================
// Kernel 3: split-fp16 HMMA GEMM. CTA 256x128, 8 warps (64x64 warp tile),
// K-chunk 64, 2-stage cp.async.
//   two_term = (Al != nullptr) && (n0 < 384): QKV q columns; else 1-term.
//   proj passes Al = nullptr -> 1-term everywhere.
// ============================================================================
#define A_TILE_B 36864                 // 256 * 144
#define B_TILE_B 18432                 // 128 * 144
#define STAGE_B  (2 * A_TILE_B + B_TILE_B)   // 92160
#define GEMM_SMEM (2 * STAGE_B)              // 184320

__global__ void __launch_bounds__(256, 1)
gemm2_kernel(const __half* __restrict__ Ah,
             const __half* __restrict__ Al,
             const __half* __restrict__ Bh,
             float* __restrict__ Cf,
             __half* __restrict__ Ch,
             __half* __restrict__ Cl,
             int ldc,
             const float* __restrict__ bias) {
    extern __shared__ __align__(16) char smem[];
    const int tid  = threadIdx.x;
    const int warp = tid >> 5;
    const int lane = tid & 31;
    const uint32_t sb = smem_to_u32(smem);
    const int m0 = blockIdx.y * 256;
    const int n0 = blockIdx.x * 128;
    const int m_warp = (warp >> 1) * 64;   // 0,64,128,192
    const int n_warp = (warp & 1) * 64;    // 0,64
    const bool two_term = (Al != nullptr) && (n0 < DIMC);

    float acc[4][8][4];
    #pragma unroll
    for (int mt = 0; mt < 4; ++mt)
        #pragma unroll
        for (int nt = 0; nt < 8; ++nt)
            #pragma unroll
            for (int e = 0; e < 4; ++e) acc[mt][nt][e] = 0.f;

    auto load_stage = [&](int stage, int ks) {
        const int k0 = ks * 64;
        const uint32_t base = sb + stage * STAGE_B;
        {                                      // Ah: 2048 chunks
            const char* src = (const char*)(Ah + (size_t)m0 * DIMC + k0);
            #pragma unroll
            for (int i = 0; i < 8; ++i) {
                int u = tid + i * 256;
                int row = u >> 3, ch = u & 7;
                cp16(base + row * 144 + ch * 16,
                     src + (size_t)row * (DIMC * 2) + ch * 16);
            }
        }
        if (two_term) {                        // Al: 2048 chunks
            const char* src = (const char*)(Al + (size_t)m0 * DIMC + k0);
            uint32_t dst = base + A_TILE_B;
            #pragma unroll
            for (int i = 0; i < 8; ++i) {
                int u = tid + i * 256;
                int row = u >> 3, ch = u & 7;
                cp16(dst + row * 144 + ch * 16,
                     src + (size_t)row * (DIMC * 2) + ch * 16);
            }
        }
        {                                      // Bh: 1024 chunks
            const char* src = (const char*)(Bh + (size_t)n0 * DIMC + k0);
            uint32_t dst = base + 2 * A_TILE_B;
            #pragma unroll
            for (int i = 0; i < 4; ++i) {
                int u = tid + i * 256;
                int row = u >> 3, ch = u & 7;
                cp16(dst + row * 144 + ch * 16,
                     src + (size_t)row * (DIMC * 2) + ch * 16);
            }
        }
    };

    load_stage(0, 0);
    CP_COMMIT();

    const int NKS = DIMC / 64;   // 6
    for (int ks = 0; ks < NKS; ++ks) {
        const int s = ks & 1;
        __syncthreads();
        if (ks + 1 < NKS) {
            load_stage(1 - s, ks + 1);
            CP_COMMIT();
            CP_WAIT(1);
        } else {
            CP_WAIT(0);
        }
        __syncthreads();

        const uint32_t ahBase = sb + s * STAGE_B;
        const uint32_t alBase = ahBase + A_TILE_B;
        const uint32_t bhBase = ahBase + 2 * A_TILE_B;
        const int rB = lane & 7, jB = (lane >> 3) & 1;
        const int rA = lane & 7, jA8 = ((lane >> 3) & 1) * 8, kA16 = ((lane >> 4) & 1) * 16;

        #pragma unroll
        for (int kk = 0; kk < 4; ++kk) {
            uint32_t ah[4][4];
            #pragma unroll
            for (int mt = 0; mt < 4; ++mt) {
                uint32_t off = (uint32_t)(m_warp + mt * 16 + jA8 + rA) * 144 + kk * 32 + kA16;
                ldsm_x4(ah[mt][0], ah[mt][1], ah[mt][2], ah[mt][3], ahBase + off);
            }
            uint32_t bh[8][2];
            #pragma unroll
            for (int nt = 0; nt < 8; ++nt) {
                uint32_t off = (uint32_t)(n_warp + nt * 8 + rB) * 144 + kk * 32 + jB * 16;
                ldsm_x2(bh[nt][0], bh[nt][1], bhBase + off);
            }
            #pragma unroll
            for (int mt = 0; mt < 4; ++mt)
                #pragma unroll
                for (int nt = 0; nt < 8; ++nt)
                    mma_f16(acc[mt][nt], ah[mt], bh[nt]);
            if (two_term) {
                uint32_t al[4][4];
                #pragma unroll
                for (int mt = 0; mt < 4; ++mt) {
                    uint32_t off = (uint32_t)(m_warp + mt * 16 + jA8 + rA) * 144 + kk * 32 + kA16;
                    ldsm_x4(al[mt][0], al[mt][1], al[mt][2], al[mt][3], alBase + off);
                }
                #pragma unroll
                for (int mt = 0; mt < 4; ++mt)
                    #pragma unroll
                    for (int nt = 0; nt < 8; ++nt)
                        mma_f16(acc[mt][nt], al[mt], bh[nt]);
            }
        }
    }

    const int mrow  = m0 + m_warp + (lane >> 2);
    const int ncol0 = n0 + n_warp + (lane & 3) * 2;
    if (Cf) {
        #pragma unroll
        for (int mt = 0; mt < 4; ++mt) {
            #pragma unroll
            for (int nt = 0; nt < 8; ++nt) {
                int m = mrow + mt * 16;
                int n = ncol0 + nt * 8;
                float2 v0 = { acc[mt][nt][0], acc[mt][nt][1] };
                float2 v1 = { acc[mt][nt][2], acc[mt][nt][3] };
                if (bias) {
                    float2 bv = *(const float2*)&bias[n];
                    v0.x += bv.x; v0.y += bv.y; v1.x += bv.x; v1.y += bv.y;
                }
                *(float2*)&Cf[(size_t)m * ldc + n]       = v0;
                *(float2*)&Cf[(size_t)(m + 8) * ldc + n] = v1;
            }
        }
    } else {
        #pragma unroll
        for (int mt = 0; mt < 4; ++mt) {
            #pragma unroll
            for (int nt = 0; nt < 8; ++nt) {
                int m = mrow + mt * 16;
                int n = ncol0 + nt * 8;
                bool isq = (n < DIMC);
                float sc = isq ? SCALEF : 1.0f;   // q columns pre-scaled
                uint32_t ph, pl;
                pack_split_h(acc[mt][nt][0] * sc, acc[mt][nt][1] * sc, ph, pl);
                *(uint32_t*)&Ch[(size_t)m * ldc + n] = ph;
                if (isq) *(uint32_t*)&Cl[(size_t)m * ldc + n] = pl;
                pack_split_h(acc[mt][nt][2] * sc, acc[mt][nt][3] * sc, ph, pl);
                *(uint32_t*)&Ch[(size_t)(m + 8) * ldc + n] = ph;
                if (isq) *(uint32_t*)&Cl[(size_t)(m + 8) * ldc + n] = pl;
            }
        }
    }
}

// ============================================================================
// Kernel 4: HMMA attention, 2-term fp16, frag-layout bias; fp16-only output.
// smem (20 KB): Qh@0 Ql@5120 Kh@10240 Vh@15360 (64 rows x 80B).
// ============================================================================
#define ATT_SMEM 20480

__global__ void __launch_bounds__(128, 5)
attn_kernel(const __half* __restrict__ qkvh,
            const __half* __restrict__ qkvl,
            const float4* __restrict__ bias_frag,
            __half* __restrict__ oh) {
    extern __shared__ __align__(16) char smem[];
    const uint32_t sb = smem_to_u32(smem);

    const int tid  = threadIdx.x;
    const int warp = tid >> 5;
    const int lane = tid & 31;
    const int head = blockIdx.x;
    const size_t base = (size_t)blockIdx.y * NW;

    // ---- zero V pad rows 49-63 (75 uint4) ----
    {
        uint4 z = {0, 0, 0, 0};
        for (int i = tid; i < 75; i += 128) {
            int rr = i / 5, cc = i % 5;
            *(uint4*)(smem + 15360 + (49 + rr) * 80 + cc * 16) = z;
        }
    }

    // ---- copy qh/ql/kh/vh: 784 x 16B chunks ----
    #pragma unroll
    for (int it = 0; it < 7; ++it) {
        int c = tid + it * 128;
        if (c < NW * 16) {
            int r = c / 16, rem = c & 15;
            int arr = rem >> 2, ch = rem & 3;      // 0:qh 1:ql 2:kh 3:vh
            const __half* src = (arr == 1) ? qkvl : qkvh;
            int seg = (arr < 2) ? 0 : (arr == 2 ? 1 : 2);
            const char* s = (const char*)(src + (base + r) * NQKV + seg * DIMC
                                          + head * HD) + ch * 16;
            *(uint4*)(smem + (uint32_t)arr * 5120u + r * 80 + ch * 16) = *(const uint4*)s;
        }
    }
    __syncthreads();

    const int rA = lane & 7, jA8 = ((lane >> 3) & 1) * 8, kA16 = ((lane >> 4) & 1) * 16;
    const int rB4 = (lane & 7) + ((lane >> 4) << 3);
    const int kB16 = ((lane >> 3) & 1) * 16;

    // ---- phase 1: S = (Qh+Ql) Kh  (M=16/warp, N=56, K=32) ----
    float s[7][4];
    #pragma unroll
    for (int j = 0; j < 7; ++j)
        #pragma unroll
        for (int e = 0; e < 4; ++e) s[j][e] = 0.f;

    #pragma unroll
    for (int kk = 0; kk < 2; ++kk) {
        uint32_t offA = (uint32_t)(16 * warp + jA8 + rA) * 80 + kk * 32 + kA16;
        uint32_t qh[4], ql[4];
        ldsm_x4(qh[0], qh[1], qh[2], qh[3], sb + offA);
        ldsm_x4(ql[0], ql[1], ql[2], ql[3], sb + 5120 + offA);
        uint32_t kh[7][2];
        #pragma unroll
        for (int p = 0; p < 3; ++p) {
            uint32_t off = (uint32_t)(16 * p + rB4) * 80 + kk * 32 + kB16;
            ldsm_x4(kh[2*p][0], kh[2*p][1], kh[2*p+1][0], kh[2*p+1][1], sb + 10240 + off);
        }
        {
            uint32_t off = (uint32_t)(48 + (lane & 7)) * 80 + kk * 32
                           + ((lane >> 3) & 1) * 16;
            ldsm_x2(kh[6][0], kh[6][1], sb + 10240 + off);
        }
        #pragma unroll
        for (int j = 0; j < 7; ++j) mma_f16(s[j], qh, kh[j]);
        #pragma unroll
        for (int j = 0; j < 7; ++j) mma_f16(s[j], ql, kh[j]);
    }

    // ---- phase 2 (registers): frag bias + square -> packed fp16 A + rowsum ----
    const int qd = lane >> 2;
    const int e2 = (lane & 3) * 2;
    const int r0 = 16 * warp + qd;
    const int r1 = r0 + 8;
    const bool r0v = (r0 < NW), r1v = (r1 < NW);
    const float4* bmf = bias_frag + ((size_t)(head * 4 + warp) * 7) * 32 + lane;
    uint32_t ah_t[4][4], al_t[4][4];
    float sum0 = 0.f, sum1 = 0.f;
    #pragma unroll
    for (int j = 0; j < 7; ++j) {
        int c = j * 8 + e2;
        bool c0v = (c < NW), c1v = (c + 1 < NW);
        float4 bv = __ldg(&bmf[j * 32]);
        float a00 = 0.f, a01 = 0.f, a10 = 0.f, a11 = 0.f;
        if (r0v && c0v) { float t = s[j][0] + bv.x; a00 = t * t; }
        if (r0v && c1v) { float t = s[j][1] + bv.y; a01 = t * t; }
        if (r1v && c0v) { float t = s[j][2] + bv.z; a10 = t * t; }
        if (r1v && c1v) { float t = s[j][3] + bv.w; a11 = t * t; }
        sum0 += a00 + a01;
        sum1 += a10 + a11;
        int t = j >> 1, hbase = (j & 1) * 2;
        pack_split_h(a00, a01, ah_t[t][hbase + 0], al_t[t][hbase + 0]);
        pack_split_h(a10, a11, ah_t[t][hbase + 1], al_t[t][hbase + 1]);
    }
    ah_t[3][2] = 0u; ah_t[3][3] = 0u;     // j = 7 zero band
    al_t[3][2] = 0u; al_t[3][3] = 0u;
    sum0 += __shfl_xor_sync(0xFFFFFFFFu, sum0, 1);
    sum0 += __shfl_xor_sync(0xFFFFFFFFu, sum0, 2);
    sum1 += __shfl_xor_sync(0xFFFFFFFFu, sum1, 1);
    sum1 += __shfl_xor_sync(0xFFFFFFFFu, sum1, 2);
    const float rs0 = 1.0f / (sum0 + 1e-6f);
    const float rs1 = 1.0f / (sum1 + 1e-6f);

    // ---- phase 3: O = (A2h+A2l) Vh  (M=16/warp, N=32, K=64) ----
    float o[4][4];
    #pragma unroll
    for (int n = 0; n < 4; ++n)
        #pragma unroll
        for (int e = 0; e < 4; ++e) o[n][e] = 0.f;

    #pragma unroll
    for (int kk = 0; kk < 4; ++kk) {
        int kv = kk * 16 + ((lane >> 3) & 1) * 8 + (lane & 7);
        uint32_t off0 = (uint32_t)kv * 80 + ((lane >> 4) * 8) * 2;
        uint32_t off1 = off0 + 32;
        uint32_t vh[4][2];
        ldsm_x4t(vh[0][0], vh[0][1], vh[1][0], vh[1][1], sb + 15360 + off0);
        ldsm_x4t(vh[2][0], vh[2][1], vh[3][0], vh[3][1], sb + 15360 + off1);
        #pragma unroll
        for (int n = 0; n < 4; ++n) mma_f16(o[n], ah_t[kk], vh[n]);
        #pragma unroll
        for (int n = 0; n < 4; ++n) mma_f16(o[n], al_t[kk], vh[n]);
    }

    // ---- phase 4: normalize + fp16 store (hi only; proj is 1-term) ----
    #pragma unroll
    for (int n = 0; n < 4; ++n) {
        int d = n * 8 + e2;
        if (r0v) {
            float2 v = { o[n][0] * rs0, o[n][1] * rs0 };
            __half2 hv = __float22half2_rn(v);
            size_t oi = (base + r0) * DIMC + head * HD + d;
            *(__half2*)&oh[oi] = hv;
        }
        if (r1v) {
            float2 v = { o[n][2] * rs1, o[n][3] * rs1 };
            __half2 hv = __float22half2_rn(v);
            size_t oi = (base + r1) * DIMC + head * HD + d;
            *(__half2*)&oh[oi] = hv;
        }
    }
}

// ============================================================================
// launch — attn is the 4th launch (profiled slot)
// ============================================================================
extern "C" void kernel_launch(void* const* d_in, const int* in_sizes, int n_in,
                              void* d_out, int out_size) {
    const float* x          = (const float*)d_in[0];
    const float* w_qkv      = (const float*)d_in[1];
    const float* w_proj     = (const float*)d_in[2];
    const float* b_proj     = (const float*)d_in[3];
    const float* bias_table = (const float*)d_in[4];
    const int*   rel_idx    = (const int*)d_in[5];
    float* out = (float*)d_out;

    void *p_xh, *p_xl, *p_wq, *p_wp, *p_qh, *p_ql, *p_ah, *p_bf;
    cudaGetSymbolAddress(&p_xh, g_xh);
    cudaGetSymbolAddress(&p_xl, g_xl);
    cudaGetSymbolAddress(&p_wq, g_wqkvT);
    cudaGetSymbolAddress(&p_wp, g_wprojT);
    cudaGetSymbolAddress(&p_qh, g_qkvh);
    cudaGetSymbolAddress(&p_ql, g_qkvl);
    cudaGetSymbolAddress(&p_ah, g_ah);
    cudaGetSymbolAddress(&p_bf, g_bias_frag);

    cudaFuncSetAttribute(gemm2_kernel,
                         cudaFuncAttributeMaxDynamicSharedMemorySize, GEMM_SMEM);

    // (1) split x -> fp16 h+l
    int n4 = (MTOT * DIMC) / 4;
    split_x_kernel<<<n4 / 256, 256>>>(x, (__half*)p_xh, (__half*)p_xl, n4);

    // (2) prep: weights + frag bias
    prep_kernel<<<PREP_BF, 256>>>(w_qkv, w_proj, bias_table, rel_idx,
        (__half*)p_wq, (__half*)p_wp, (float4*)p_bf);

    // (3) QKV GEMM (q cols 2-term, k/v cols 1-term)
    gemm2_kernel<<<dim3(NQKV / 128, MTOT / 256), 256, GEMM_SMEM>>>(
        (const __half*)p_xh, (const __half*)p_xl, (const __half*)p_wq,
        nullptr, (__half*)p_qh, (__half*)p_ql, NQKV, nullptr);

    // (4) attention  <-- profiled slot
    attn_kernel<<<dim3(NH, MTOT / NW), 128, ATT_SMEM>>>(
        (const __half*)p_qh, (const __half*)p_ql,
        (const float4*)p_bf, (__half*)p_ah);

    // (5) proj GEMM (1-term) + bias -> out (fp32)
    gemm2_kernel<<<dim3(DIMC / 128, MTOT / 256), 256, GEMM_SMEM>>>(
        (const __half*)p_ah, nullptr, (const __half*)p_wp,
        out, nullptr, nullptr, DIMC, b_proj);
}

// round 16
// speedup vs baseline: 1.9306x; 1.0287x over previous
#include <cuda_runtime.h>
#include <cuda_fp16.h>
#include <cstdint>

// ============================================================================
// Swin window attention (quadratic norm), split-fp16 HMMA pipeline:
//   q GEMM: 2-term (xh+xl)@Wq, N=384           (gemm2, K-chunk 64)
//   kv GEMM: 1-term xh@Wkv, N=768              (gemm1, K-chunk 128)
//   attention: HMMA, register A frags, frag-layout bias; fp16 out
//   proj: 1-term ah@Wp + bias -> fp32          (gemm1, K-chunk 128)
// Launch: split_x, prep, gemm2-q, gemm1-kv [slot 4], attn, gemm1-proj.
// ============================================================================

#define NW     49
#define DIMC   384
#define NH     12
#define HD     32
#define SCALEF 0.17677669529663687f
#define MTOT   200704            // 4096 * 49 = 784 * 256
#define NQKV   1152

// ---- scratch (device globals) -----------------------------------------------
__device__ __half g_xh[(size_t)MTOT * DIMC];
__device__ __half g_xl[(size_t)MTOT * DIMC];
__device__ __half g_wqkvT[NQKV * DIMC];
__device__ __half g_wprojT[DIMC * DIMC];
__device__ __half g_qkvh[(size_t)MTOT * NQKV];
__device__ __half g_qkvl[(size_t)MTOT * NQKV];   // only q cols (0..383) used
__device__ __half g_ah[(size_t)MTOT * DIMC];
__device__ float4 g_bias_frag[NH * 4 * 7 * 32];  // [h][warp][j][lane]

// ---- helpers ------------------------------------------------------------------
__device__ __forceinline__ uint32_t smem_to_u32(const void* p) {
    uint32_t a;
    asm("{ .reg .u64 t; cvta.to.shared.u64 t, %1; cvt.u32.u64 %0, t; }"
        : "=r"(a) : "l"(p));
    return a;
}
__device__ __forceinline__ void ldsm_x4(uint32_t& r0, uint32_t& r1,
                                        uint32_t& r2, uint32_t& r3, uint32_t a) {
    asm volatile("ldmatrix.sync.aligned.m8n8.x4.shared.b16 {%0,%1,%2,%3}, [%4];"
                 : "=r"(r0), "=r"(r1), "=r"(r2), "=r"(r3) : "r"(a));
}
__device__ __forceinline__ void ldsm_x2(uint32_t& r0, uint32_t& r1, uint32_t a) {
    asm volatile("ldmatrix.sync.aligned.m8n8.x2.shared.b16 {%0,%1}, [%2];"
                 : "=r"(r0), "=r"(r1) : "r"(a));
}
__device__ __forceinline__ void ldsm_x4t(uint32_t& r0, uint32_t& r1,
                                         uint32_t& r2, uint32_t& r3, uint32_t a) {
    asm volatile("ldmatrix.sync.aligned.m8n8.x4.trans.shared.b16 {%0,%1,%2,%3}, [%4];"
                 : "=r"(r0), "=r"(r1), "=r"(r2), "=r"(r3) : "r"(a));
}
__device__ __forceinline__ void mma_f16(float* d, const uint32_t* a, const uint32_t* b) {
    asm volatile("mma.sync.aligned.m16n8k16.row.col.f32.f16.f16.f32 "
                 "{%0,%1,%2,%3}, {%4,%5,%6,%7}, {%8,%9}, {%0,%1,%2,%3};"
                 : "+f"(d[0]), "+f"(d[1]), "+f"(d[2]), "+f"(d[3])
                 : "r"(a[0]), "r"(a[1]), "r"(a[2]), "r"(a[3]), "r"(b[0]), "r"(b[1]));
}
__device__ __forceinline__ void cp16(uint32_t dst, const void* src) {
    asm volatile("cp.async.cg.shared.global [%0], [%1], 16;" :: "r"(dst), "l"(src));
}
#define CP_COMMIT() asm volatile("cp.async.commit_group;" ::: "memory")
#define CP_WAIT(n)  asm volatile("cp.async.wait_group %0;" :: "n"(n) : "memory")

__device__ __forceinline__ void split2h(float v, __half& h, __half& l) {
    h = __float2half_rn(v);
    l = __float2half_rn(v - __half2float(h));
}
__device__ __forceinline__ void pack_split_h(float a, float b, uint32_t& ph, uint32_t& pl) {
    __half ha, la, hb, lb;
    split2h(a, ha, la); split2h(b, hb, lb);
    __half2 vh = { ha, hb }, vl = { la, lb };
    ph = *(uint32_t*)&vh;
    pl = *(uint32_t*)&vl;
}

// ============================================================================
// Kernel 1: split x (fp32 -> fp16 hi/lo)
// ============================================================================
__global__ void split_x_kernel(const float* __restrict__ x,
                               __half* __restrict__ xh,
                               __half* __restrict__ xl, int n4) {
    int i = blockIdx.x * 256 + threadIdx.x;
    if (i >= n4) return;
    float4 v = ((const float4*)x)[i];
    __half h0, h1, h2, h3, l0, l1, l2, l3;
    split2h(v.x, h0, l0); split2h(v.y, h1, l1);
    split2h(v.z, h2, l2); split2h(v.w, h3, l3);
    ushort4 hv = { __half_as_ushort(h0), __half_as_ushort(h1),
                   __half_as_ushort(h2), __half_as_ushort(h3) };
    ushort4 lv = { __half_as_ushort(l0), __half_as_ushort(l1),
                   __half_as_ushort(l2), __half_as_ushort(l3) };
    ((ushort4*)xh)[i] = hv;
    ((ushort4*)xl)[i] = lv;
}

// ============================================================================
// Kernel 2: prep — w -> fp16 transposed; bias -> fragment layout.
// ============================================================================
#define PREP_WQ 1728
#define PREP_WP (PREP_WQ + 576)
#define PREP_BF (PREP_WP + 42)

__global__ void prep_kernel(const float* __restrict__ wqkv,
                            const float* __restrict__ wproj,
                            const float* __restrict__ bt,
                            const int* __restrict__ rel,
                            __half* __restrict__ wq,
                            __half* __restrict__ wp,
                            float4* __restrict__ bmf) {
    int b = blockIdx.x;
    if (b < PREP_WQ) {
        int i = b * 256 + threadIdx.x;
        int n = i / DIMC, k = i - n * DIMC;
        wq[i] = __float2half_rn(wqkv[(size_t)k * NQKV + n]);
    } else if (b < PREP_WP) {
        int i = (b - PREP_WQ) * 256 + threadIdx.x;
        int n = i / DIMC, k = i - n * DIMC;
        wp[i] = __float2half_rn(wproj[(size_t)k * DIMC + n]);
    } else {
        int i = (b - PREP_WP) * 256 + threadIdx.x;
        if (i < NH * 4 * 7 * 32) {
            int lane = i & 31;
            int j = (i >> 5) % 7;
            int w = (i / (32 * 7)) % 4;
            int h = i / (32 * 7 * 4);
            int qd = lane >> 2, e2 = (lane & 3) * 2;
            int r0 = 16 * w + qd, r1 = r0 + 8;
            int c = 8 * j + e2;
            float4 v = { 0.f, 0.f, 0.f, 0.f };
            if (r0 < NW && c < NW)     v.x = bt[rel[r0 * NW + c] * NH + h];
            if (r0 < NW && c + 1 < NW) v.y = bt[rel[r0 * NW + c + 1] * NH + h];
            if (r1 < NW && c < NW)     v.z = bt[rel[r1 * NW + c] * NH + h];
            if (r1 < NW && c + 1 < NW) v.w = bt[rel[r1 * NW + c + 1] * NH + h];
            bmf[i] = v;
        }
    }
}

// ============================================================================
// Kernel 3: gemm2 — 2-term (Ah+Al)@Bh, CTA 256x128, K-chunk 64. q GEMM only.
// Output: fp16 Ch+Cl, scaled by SCALEF (all columns are q).
// ============================================================================
#define A_TILE_B 36864
#define B_TILE_B 18432
#define STAGE_B  (2 * A_TILE_B + B_TILE_B)   // 92160
#define GEMM2_SMEM (2 * STAGE_B)             // 184320

__global__ void __launch_bounds__(256, 1)
gemm2_kernel(const __half* __restrict__ Ah,
             const __half* __restrict__ Al,
             const __half* __restrict__ Bh,
             __half* __restrict__ Ch,
             __half* __restrict__ Cl,
             int ldc) {
    extern __shared__ __align__(16) char smem[];
    const int tid  = threadIdx.x;
    const int warp = tid >> 5;
    const int lane = tid & 31;
    const uint32_t sb = smem_to_u32(smem);
    const int m0 = blockIdx.y * 256;
    const int n0 = blockIdx.x * 128;
    const int m_warp = (warp >> 1) * 64;
    const int n_warp = (warp & 1) * 64;

    float acc[4][8][4];
    #pragma unroll
    for (int mt = 0; mt < 4; ++mt)
        #pragma unroll
        for (int nt = 0; nt < 8; ++nt)
            #pragma unroll
            for (int e = 0; e < 4; ++e) acc[mt][nt][e] = 0.f;

    auto load_stage = [&](int stage, int ks) {
        const int k0 = ks * 64;
        const uint32_t base = sb + stage * STAGE_B;
        #pragma unroll
        for (int t = 0; t < 2; ++t) {
            const char* src = (const char*)((t ? Al : Ah) + (size_t)m0 * DIMC + k0);
            uint32_t dst = base + t * A_TILE_B;
            #pragma unroll
            for (int i = 0; i < 8; ++i) {
                int u = tid + i * 256;
                int row = u >> 3, ch = u & 7;
                cp16(dst + row * 144 + ch * 16,
                     src + (size_t)row * (DIMC * 2) + ch * 16);
            }
        }
        {
            const char* src = (const char*)(Bh + (size_t)n0 * DIMC + k0);
            uint32_t dst = base + 2 * A_TILE_B;
            #pragma unroll
            for (int i = 0; i < 4; ++i) {
                int u = tid + i * 256;
                int row = u >> 3, ch = u & 7;
                cp16(dst + row * 144 + ch * 16,
                     src + (size_t)row * (DIMC * 2) + ch * 16);
            }
        }
    };

    load_stage(0, 0);
    CP_COMMIT();

    const int NKS = DIMC / 64;   // 6
    for (int ks = 0; ks < NKS; ++ks) {
        const int s = ks & 1;
        __syncthreads();
        if (ks + 1 < NKS) {
            load_stage(1 - s, ks + 1);
            CP_COMMIT();
            CP_WAIT(1);
        } else {
            CP_WAIT(0);
        }
        __syncthreads();

        const uint32_t ahBase = sb + s * STAGE_B;
        const uint32_t alBase = ahBase + A_TILE_B;
        const uint32_t bhBase = ahBase + 2 * A_TILE_B;
        const int rB = lane & 7, jB = (lane >> 3) & 1;
        const int rA = lane & 7, jA8 = ((lane >> 3) & 1) * 8, kA16 = ((lane >> 4) & 1) * 16;

        #pragma unroll
        for (int kk = 0; kk < 4; ++kk) {
            uint32_t ah[4][4], al[4][4];
            #pragma unroll
            for (int mt = 0; mt < 4; ++mt) {
                uint32_t off = (uint32_t)(m_warp + mt * 16 + jA8 + rA) * 144 + kk * 32 + kA16;
                ldsm_x4(ah[mt][0], ah[mt][1], ah[mt][2], ah[mt][3], ahBase + off);
                ldsm_x4(al[mt][0], al[mt][1], al[mt][2], al[mt][3], alBase + off);
            }
            uint32_t bh[8][2];
            #pragma unroll
            for (int nt = 0; nt < 8; ++nt) {
                uint32_t off = (uint32_t)(n_warp + nt * 8 + rB) * 144 + kk * 32 + jB * 16;
                ldsm_x2(bh[nt][0], bh[nt][1], bhBase + off);
            }
            #pragma unroll
            for (int mt = 0; mt < 4; ++mt)
                #pragma unroll
                for (int nt = 0; nt < 8; ++nt)
                    mma_f16(acc[mt][nt], ah[mt], bh[nt]);
            #pragma unroll
            for (int mt = 0; mt < 4; ++mt)
                #pragma unroll
                for (int nt = 0; nt < 8; ++nt)
                    mma_f16(acc[mt][nt], al[mt], bh[nt]);
        }
    }

    const int mrow  = m0 + m_warp + (lane >> 2);
    const int ncol0 = n0 + n_warp + (lane & 3) * 2;
    #pragma unroll
    for (int mt = 0; mt < 4; ++mt) {
        #pragma unroll
        for (int nt = 0; nt < 8; ++nt) {
            int m = mrow + mt * 16;
            int n = ncol0 + nt * 8;
            uint32_t ph, pl;
            pack_split_h(acc[mt][nt][0] * SCALEF, acc[mt][nt][1] * SCALEF, ph, pl);
            *(uint32_t*)&Ch[(size_t)m * ldc + n] = ph;
            *(uint32_t*)&Cl[(size_t)m * ldc + n] = pl;
            pack_split_h(acc[mt][nt][2] * SCALEF, acc[mt][nt][3] * SCALEF, ph, pl);
            *(uint32_t*)&Ch[(size_t)(m + 8) * ldc + n] = ph;
            *(uint32_t*)&Cl[(size_t)(m + 8) * ldc + n] = pl;
        }
    }
}

// ============================================================================
// Kernel 4: gemm1 — 1-term Ah@Bh, CTA 256x128, K-chunk 128 (272B rows,
// 2 stages = 204 KB smem, 3 k-steps). Used for kv GEMM and proj GEMM.
// Epilogue: Cf -> fp32 (+bias) or Ch -> fp16 (unscaled).
// ============================================================================
#define A_TILE1 69632                  // 256 * 272
#define B_TILE1 34816                  // 128 * 272
#define STAGE1  (A_TILE1 + B_TILE1)    // 104448
#define GEMM1_SMEM (2 * STAGE1)        // 208896

__global__ void __launch_bounds__(256, 1)
gemm1_kernel(const __half* __restrict__ Ah,
             const __half* __restrict__ Bh,
             float* __restrict__ Cf,
             __half* __restrict__ Ch,
             int ldc,
             const float* __restrict__ bias) {
    extern __shared__ __align__(16) char smem[];
    const int tid  = threadIdx.x;
    const int warp = tid >> 5;
    const int lane = tid & 31;
    const uint32_t sb = smem_to_u32(smem);
    const int m0 = blockIdx.y * 256;
    const int n0 = blockIdx.x * 128;
    const int m_warp = (warp >> 1) * 64;
    const int n_warp = (warp & 1) * 64;

    float acc[4][8][4];
    #pragma unroll
    for (int mt = 0; mt < 4; ++mt)
        #pragma unroll
        for (int nt = 0; nt < 8; ++nt)
            #pragma unroll
            for (int e = 0; e < 4; ++e) acc[mt][nt][e] = 0.f;

    auto load_stage = [&](int stage, int ks) {
        const int k0 = ks * 128;
        const uint32_t base = sb + stage * STAGE1;
        {   // A: 256 rows x 16 chunks = 4096
            const char* src = (const char*)(Ah + (size_t)m0 * DIMC + k0);
            #pragma unroll
            for (int i = 0; i < 16; ++i) {
                int u = tid + i * 256;
                int row = u >> 4, ch = u & 15;
                cp16(base + row * 272 + ch * 16,
                     src + (size_t)row * (DIMC * 2) + ch * 16);
            }
        }
        {   // B: 128 rows x 16 chunks = 2048
            const char* src = (const char*)(Bh + (size_t)n0 * DIMC + k0);
            uint32_t dst = base + A_TILE1;
            #pragma unroll
            for (int i = 0; i < 8; ++i) {
                int u = tid + i * 256;
                int row = u >> 4, ch = u & 15;
                cp16(dst + row * 272 + ch * 16,
                     src + (size_t)row * (DIMC * 2) + ch * 16);
            }
        }
    };

    load_stage(0, 0);
    CP_COMMIT();

    const int NKS = DIMC / 128;   // 3
    for (int ks = 0; ks < NKS; ++ks) {
        const int s = ks & 1;
        __syncthreads();
        if (ks + 1 < NKS) {
            load_stage(1 - s, ks + 1);
            CP_COMMIT();
            CP_WAIT(1);
        } else {
            CP_WAIT(0);
        }
        __syncthreads();

        const uint32_t aBase = sb + s * STAGE1;
        const uint32_t bBase = aBase + A_TILE1;
        const int rB = lane & 7, jB = (lane >> 3) & 1;
        const int rA = lane & 7, jA8 = ((lane >> 3) & 1) * 8, kA16 = ((lane >> 4) & 1) * 16;

        #pragma unroll
        for (int kk = 0; kk < 8; ++kk) {
            uint32_t ah[4][4];
            #pragma unroll
            for (int mt = 0; mt < 4; ++mt) {
                uint32_t off = (uint32_t)(m_warp + mt * 16 + jA8 + rA) * 272 + kk * 32 + kA16;
                ldsm_x4(ah[mt][0], ah[mt][1], ah[mt][2], ah[mt][3], aBase + off);
            }
            uint32_t bh[8][2];
            #pragma unroll
            for (int nt = 0; nt < 8; ++nt) {
                uint32_t off = (uint32_t)(n_warp + nt * 8 + rB) * 272 + kk * 32 + jB * 16;
                ldsm_x2(bh[nt][0], bh[nt][1], bBase + off);
            }
            #pragma unroll
            for (int mt = 0; mt < 4; ++mt)
                #pragma unroll
                for (int nt = 0; nt < 8; ++nt)
                    mma_f16(acc[mt][nt], ah[mt], bh[nt]);
        }
    }

    const int mrow  = m0 + m_warp + (lane >> 2);
    const int ncol0 = n0 + n_warp + (lane & 3) * 2;
    if (Cf) {
        #pragma unroll
        for (int mt = 0; mt < 4; ++mt) {
            #pragma unroll
            for (int nt = 0; nt < 8; ++nt) {
                int m = mrow + mt * 16;
                int n = ncol0 + nt * 8;
                float2 bv = *(const float2*)&bias[n];
                float2 v0 = { acc[mt][nt][0] + bv.x, acc[mt][nt][1] + bv.y };
                float2 v1 = { acc[mt][nt][2] + bv.x, acc[mt][nt][3] + bv.y };
                *(float2*)&Cf[(size_t)m * ldc + n]       = v0;
                *(float2*)&Cf[(size_t)(m + 8) * ldc + n] = v1;
            }
        }
    } else {
        #pragma unroll
        for (int mt = 0; mt < 4; ++mt) {
            #pragma unroll
            for (int nt = 0; nt < 8; ++nt) {
                int m = mrow + mt * 16;
                int n = ncol0 + nt * 8;
                float2 v0 = { acc[mt][nt][0], acc[mt][nt][1] };
                float2 v1 = { acc[mt][nt][2], acc[mt][nt][3] };
                *(__half2*)&Ch[(size_t)m * ldc + n]       = __float22half2_rn(v0);
                *(__half2*)&Ch[(size_t)(m + 8) * ldc + n] = __float22half2_rn(v1);
            }
        }
    }
}

// ============================================================================
// Kernel 5: HMMA attention (unchanged from R14).
// ============================================================================
#define ATT_SMEM 20480

__global__ void __launch_bounds__(128, 5)
attn_kernel(const __half* __restrict__ qkvh,
            const __half* __restrict__ qkvl,
            const float4* __restrict__ bias_frag,
            __half* __restrict__ oh) {
    extern __shared__ __align__(16) char smem[];
    const uint32_t sb = smem_to_u32(smem);

    const int tid  = threadIdx.x;
    const int warp = tid >> 5;
    const int lane = tid & 31;
    const int head = blockIdx.x;
    const size_t base = (size_t)blockIdx.y * NW;

    {
        uint4 z = {0, 0, 0, 0};
        for (int i = tid; i < 75; i += 128) {
            int rr = i / 5, cc = i % 5;
            *(uint4*)(smem + 15360 + (49 + rr) * 80 + cc * 16) = z;
        }
    }
    #pragma unroll
    for (int it = 0; it < 7; ++it) {
        int c = tid + it * 128;
        if (c < NW * 16) {
            int r = c / 16, rem = c & 15;
            int arr = rem >> 2, ch = rem & 3;
            const __half* src = (arr == 1) ? qkvl : qkvh;
            int seg = (arr < 2) ? 0 : (arr == 2 ? 1 : 2);
            const char* s = (const char*)(src + (base + r) * NQKV + seg * DIMC
                                          + head * HD) + ch * 16;
            *(uint4*)(smem + (uint32_t)arr * 5120u + r * 80 + ch * 16) = *(const uint4*)s;
        }
    }
    __syncthreads();

    const int rA = lane & 7, jA8 = ((lane >> 3) & 1) * 8, kA16 = ((lane >> 4) & 1) * 16;
    const int rB4 = (lane & 7) + ((lane >> 4) << 3);
    const int kB16 = ((lane >> 3) & 1) * 16;

    float s[7][4];
    #pragma unroll
    for (int j = 0; j < 7; ++j)
        #pragma unroll
        for (int e = 0; e < 4; ++e) s[j][e] = 0.f;

    #pragma unroll
    for (int kk = 0; kk < 2; ++kk) {
        uint32_t offA = (uint32_t)(16 * warp + jA8 + rA) * 80 + kk * 32 + kA16;
        uint32_t qh[4], ql[4];
        ldsm_x4(qh[0], qh[1], qh[2], qh[3], sb + offA);
        ldsm_x4(ql[0], ql[1], ql[2], ql[3], sb + 5120 + offA);
        uint32_t kh[7][2];
        #pragma unroll
        for (int p = 0; p < 3; ++p) {
            uint32_t off = (uint32_t)(16 * p + rB4) * 80 + kk * 32 + kB16;
            ldsm_x4(kh[2*p][0], kh[2*p][1], kh[2*p+1][0], kh[2*p+1][1], sb + 10240 + off);
        }
        {
            uint32_t off = (uint32_t)(48 + (lane & 7)) * 80 + kk * 32
                           + ((lane >> 3) & 1) * 16;
            ldsm_x2(kh[6][0], kh[6][1], sb + 10240 + off);
        }
        #pragma unroll
        for (int j = 0; j < 7; ++j) mma_f16(s[j], qh, kh[j]);
        #pragma unroll
        for (int j = 0; j < 7; ++j) mma_f16(s[j], ql, kh[j]);
    }

    const int qd = lane >> 2;
    const int e2 = (lane & 3) * 2;
    const int r0 = 16 * warp + qd;
    const int r1 = r0 + 8;
    const bool r0v = (r0 < NW), r1v = (r1 < NW);
    const float4* bmf = bias_frag + ((size_t)(head * 4 + warp) * 7) * 32 + lane;
    uint32_t ah_t[4][4], al_t[4][4];
    float sum0 = 0.f, sum1 = 0.f;
    #pragma unroll
    for (int j = 0; j < 7; ++j) {
        int c = j * 8 + e2;
        bool c0v = (c < NW), c1v = (c + 1 < NW);
        float4 bv = __ldg(&bmf[j * 32]);
        float a00 = 0.f, a01 = 0.f, a10 = 0.f, a11 = 0.f;
        if (r0v && c0v) { float t = s[j][0] + bv.x; a00 = t * t; }
        if (r0v && c1v) { float t = s[j][1] + bv.y; a01 = t * t; }
        if (r1v && c0v) { float t = s[j][2] + bv.z; a10 = t * t; }
        if (r1v && c1v) { float t = s[j][3] + bv.w; a11 = t * t; }
        sum0 += a00 + a01;
        sum1 += a10 + a11;
        int t = j >> 1, hbase = (j & 1) * 2;
        pack_split_h(a00, a01, ah_t[t][hbase + 0], al_t[t][hbase + 0]);
        pack_split_h(a10, a11, ah_t[t][hbase + 1], al_t[t][hbase + 1]);
    }
    ah_t[3][2] = 0u; ah_t[3][3] = 0u;
    al_t[3][2] = 0u; al_t[3][3] = 0u;
    sum0 += __shfl_xor_sync(0xFFFFFFFFu, sum0, 1);
    sum0 += __shfl_xor_sync(0xFFFFFFFFu, sum0, 2);
    sum1 += __shfl_xor_sync(0xFFFFFFFFu, sum1, 1);
    sum1 += __shfl_xor_sync(0xFFFFFFFFu, sum1, 2);
    const float rs0 = 1.0f / (sum0 + 1e-6f);
    const float rs1 = 1.0f / (sum1 + 1e-6f);

    float o[4][4];
    #pragma unroll
    for (int n = 0; n < 4; ++n)
        #pragma unroll
        for (int e = 0; e < 4; ++e) o[n][e] = 0.f;

    #pragma unroll
    for (int kk = 0; kk < 4; ++kk) {
        int kv = kk * 16 + ((lane >> 3) & 1) * 8 + (lane & 7);
        uint32_t off0 = (uint32_t)kv * 80 + ((lane >> 4) * 8) * 2;
        uint32_t off1 = off0 + 32;
        uint32_t vh[4][2];
        ldsm_x4t(vh[0][0], vh[0][1], vh[1][0], vh[1][1], sb + 15360 + off0);
        ldsm_x4t(vh[2][0], vh[2][1], vh[3][0], vh[3][1], sb + 15360 + off1);
        #pragma unroll
        for (int n = 0; n < 4; ++n) mma_f16(o[n], ah_t[kk], vh[n]);
        #pragma unroll
        for (int n = 0; n < 4; ++n) mma_f16(o[n], al_t[kk], vh[n]);
    }

    #pragma unroll
    for (int n = 0; n < 4; ++n) {
        int d = n * 8 + e2;
        if (r0v) {
            float2 v = { o[n][0] * rs0, o[n][1] * rs0 };
            size_t oi = (base + r0) * DIMC + head * HD + d;
            *(__half2*)&oh[oi] = __float22half2_rn(v);
        }
        if (r1v) {
            float2 v = { o[n][2] * rs1, o[n][3] * rs1 };
            size_t oi = (base + r1) * DIMC + head * HD + d;
            *(__half2*)&oh[oi] = __float22half2_rn(v);
        }
    }
}

// ============================================================================
// launch — gemm1-kv is the 4th launch (profiled slot)
// ============================================================================
extern "C" void kernel_launch(void* const* d_in, const int* in_sizes, int n_in,
                              void* d_out, int out_size) {
    const float* x          = (const float*)d_in[0];
    const float* w_qkv      = (const float*)d_in[1];
    const float* w_proj     = (const float*)d_in[2];
    const float* b_proj     = (const float*)d_in[3];
    const float* bias_table = (const float*)d_in[4];
    const int*   rel_idx    = (const int*)d_in[5];
    float* out = (float*)d_out;

    void *p_xh, *p_xl, *p_wq, *p_wp, *p_qh, *p_ql, *p_ah, *p_bf;
    cudaGetSymbolAddress(&p_xh, g_xh);
    cudaGetSymbolAddress(&p_xl, g_xl);
    cudaGetSymbolAddress(&p_wq, g_wqkvT);
    cudaGetSymbolAddress(&p_wp, g_wprojT);
    cudaGetSymbolAddress(&p_qh, g_qkvh);
    cudaGetSymbolAddress(&p_ql, g_qkvl);
    cudaGetSymbolAddress(&p_ah, g_ah);
    cudaGetSymbolAddress(&p_bf, g_bias_frag);

    cudaFuncSetAttribute(gemm2_kernel,
                         cudaFuncAttributeMaxDynamicSharedMemorySize, GEMM2_SMEM);
    cudaFuncSetAttribute(gemm1_kernel,
                         cudaFuncAttributeMaxDynamicSharedMemorySize, GEMM1_SMEM);

    // (1) split x -> fp16 h+l
    int n4 = (MTOT * DIMC) / 4;
    split_x_kernel<<<n4 / 256, 256>>>(x, (__half*)p_xh, (__half*)p_xl, n4);

    // (2) prep: weights + frag bias
    prep_kernel<<<PREP_BF, 256>>>(w_qkv, w_proj, bias_table, rel_idx,
        (__half*)p_wq, (__half*)p_wp, (float4*)p_bf);

    // (3) q GEMM (2-term, N=384, pre-scaled, h+l out)
    gemm2_kernel<<<dim3(DIMC / 128, MTOT / 256), 256, GEMM2_SMEM>>>(
        (const __half*)p_xh, (const __half*)p_xl, (const __half*)p_wq,
        (__half*)p_qh, (__half*)p_ql, NQKV);

    // (4) kv GEMM (1-term, K-chunk 128, N=768)  <-- profiled slot
    gemm1_kernel<<<dim3((NQKV - DIMC) / 128, MTOT / 256), 256, GEMM1_SMEM>>>(
        (const __half*)p_xh, (const __half*)p_wq + (size_t)DIMC * DIMC,
        nullptr, (__half*)p_qh + DIMC, NQKV, nullptr);

    // (5) attention
    attn_kernel<<<dim3(NH, MTOT / NW), 128, ATT_SMEM>>>(
        (const __half*)p_qh, (const __half*)p_ql,
        (const float4*)p_bf, (__half*)p_ah);

    // (6) proj GEMM (1-term, K-chunk 128) + bias -> out (fp32)
    gemm1_kernel<<<dim3(DIMC / 128, MTOT / 256), 256, GEMM1_SMEM>>>(
        (const __half*)p_ah, (const __half*)p_wp,
        out, nullptr, DIMC, b_proj);
}